// round 4
// baseline (speedup 1.0000x reference)
#include <cuda_runtime.h>
#include <cuda_fp16.h>
#include <math.h>

#define Bz   2048
#define Tz   64
#define HZ   128   // HID
#define FZ   128   // FEAT
#define NB   8     // batch rows per persistent CTA
#define NT   256   // threads per CTA

typedef unsigned long long ull;

// ---------------- scratch (static device globals) ----------------
__device__ __half2 g_sPT[(size_t)Bz * FZ * (Tz / 2)];  // [b][f][t-pair] fp16x2 (32 MB)
__device__ __half  g_Hh [(size_t)Bz * Tz * HZ];        // [b][t][h] fp16 (32 MB)
__device__ float   g_WhT[HZ * 4 * HZ];                 // Whh^T [128h][512j]
__device__ ulonglong2 g_WA [64 * 128];                 // [hp][jj] {(wi_h,wi_h1),(wf_h,wf_h1)}
__device__ ulonglong2 g_WB [64 * 128];                 // [hp][jj] {(wg_h,wg_h1),(wo_h,wo_h1)}
__device__ ulonglong2 g_W1P[64 * 128];                 // [hp][jj] {(W1d_h,W1d_h1),(W1c_h,W1c_h1)}

// ---------------- helpers ----------------
__device__ __forceinline__ float wred(float v) {
#pragma unroll
    for (int o = 16; o > 0; o >>= 1) v += __shfl_xor_sync(0xffffffffu, v, o);
    return v;
}
__device__ __forceinline__ float fast_tanh(float x) {
    float e = __expf(2.0f * x);
    return 1.0f - __fdividef(2.0f, e + 1.0f);
}
__device__ __forceinline__ float tanh_approx(float x) {
    float r; asm("tanh.approx.f32 %0, %1;" : "=f"(r) : "f"(x)); return r;
}
__device__ __forceinline__ float sigm(float x) {
    return __fdividef(1.0f, 1.0f + __expf(-x));
}
__device__ __forceinline__ ull pack2(float a, float b) {
    return (ull)__float_as_uint(a) | ((ull)__float_as_uint(b) << 32);
}
__device__ __forceinline__ float lo2(ull v) { return __uint_as_float((unsigned)v); }
__device__ __forceinline__ float hi2(ull v) { return __uint_as_float((unsigned)(v >> 32)); }
__device__ __forceinline__ void ffma2(ull &acc, ull a, ull b) {
    asm("fma.rn.f32x2 %0, %1, %2, %0;" : "+l"(acc) : "l"(a), "l"(b));
}
__device__ __forceinline__ float hsum(ull v) { return lo2(v) + hi2(v); }

// ---------------------------------------------------------------------------
// k_tr: tiled transpose Whh [512,128] -> g_WhT [128,512]
// ---------------------------------------------------------------------------
__global__ void k_tr(const float* __restrict__ Whh) {
    __shared__ float tile[32][33];
    int tx = threadIdx.x, ty = threadIdx.y;
    int x = blockIdx.x * 32 + tx;
    int y = blockIdx.y * 32 + ty;
#pragma unroll
    for (int k = 0; k < 32; k += 8)
        tile[ty + k][tx] = Whh[(y + k) * HZ + x];
    __syncthreads();
    int x2 = blockIdx.y * 32 + tx;
    int y2 = blockIdx.x * 32 + ty;
#pragma unroll
    for (int k = 0; k < 32; k += 8)
        g_WhT[(y2 + k) * 512 + x2] = tile[tx][ty + k];
}

// ---------------------------------------------------------------------------
// k_pack: build h-pair packed weight tables (24576 entries)
// ---------------------------------------------------------------------------
__global__ void k_pack(const float* __restrict__ W1) {
    int idx = blockIdx.x * 256 + threadIdx.x;
    int e = idx & 8191;
    int hp = e >> 7, jj = e & 127;
    int h0 = 2 * hp, h1 = 2 * hp + 1;
    if (idx < 8192) {
        g_WA[e] = make_ulonglong2(
            pack2(g_WhT[h0 * 512 + jj],       g_WhT[h1 * 512 + jj]),
            pack2(g_WhT[h0 * 512 + 128 + jj], g_WhT[h1 * 512 + 128 + jj]));
    } else if (idx < 16384) {
        g_WB[e] = make_ulonglong2(
            pack2(g_WhT[h0 * 512 + 256 + jj], g_WhT[h1 * 512 + 256 + jj]),
            pack2(g_WhT[h0 * 512 + 384 + jj], g_WhT[h1 * 512 + 384 + jj]));
    } else {
        g_W1P[e] = make_ulonglong2(
            pack2(__ldg(&W1[h0 * FZ + jj]),         __ldg(&W1[h1 * FZ + jj])),
            pack2(__ldg(&W1[(128 + h0) * FZ + jj]), __ldg(&W1[(128 + h1) * FZ + jj])));
    }
}

// ---------------------------------------------------------------------------
// k_init: g_sPT[b][f][tp] = fp16(H@W1_h + b1) transposed; g_Hh = fp16(H).
// ---------------------------------------------------------------------------
#define SMEM_INIT (HZ * 68 * 4 + 32 * 129 * 4)
__global__ void k_init(const float* __restrict__ H,
                       const float* __restrict__ W1,
                       const float* __restrict__ b1) {
    extern __shared__ char smraw[];
    float*    sHT    = (float*)smraw;                    // [128h][68pad]
    unsigned* sStage = (unsigned*)(smraw + HZ * 68 * 4); // [32tp][129pad]
    int b = blockIdx.x, tid = threadIdx.x;
    const float* Hb = H + (size_t)b * Tz * HZ;
    for (int i = tid; i < Tz * HZ; i += 256) {
        int t = i >> 7, h = i & 127;
        float v = Hb[i];
        sHT[h * 68 + t] = v;
        g_Hh[(size_t)b * Tz * HZ + i] = __float2half(v);
    }
    __syncthreads();

    int f = tid & 127, half_id = tid >> 7;
    float bias = __ldg(&b1[f]);
    ull acc[16];
#pragma unroll
    for (int k = 0; k < 16; ++k) acc[k] = pack2(bias, bias);

#pragma unroll 2
    for (int h = 0; h < HZ; ++h) {
        float w = __ldg(&W1[(256 + h) * FZ + f]);
        ull ww = pack2(w, w);
        const ull* row = (const ull*)&sHT[h * 68];
#pragma unroll
        for (int k = 0; k < 16; ++k)
            ffma2(acc[k], row[half_id * 16 + k], ww);
    }
#pragma unroll
    for (int k = 0; k < 16; ++k) {
        int tp = half_id * 16 + k;
        __half2 hv = __floats2half2_rn(lo2(acc[k]), hi2(acc[k]));
        sStage[tp * 129 + f] = *(unsigned*)&hv;
    }
    __syncthreads();
    unsigned* dst = (unsigned*)g_sPT + (size_t)b * (FZ * 32);
    for (int i = tid; i < FZ * 32; i += 256) {
        int ff = i >> 5, tp = i & 31;
        dst[i] = sStage[tp * 129 + ff];
    }
}

// ---------------------------------------------------------------------------
// k_main: persistent scan. Grid 256 CTAs x 256 threads; CTA owns NB=8 rows.
// ---------------------------------------------------------------------------
__global__ void __launch_bounds__(NT, 2)
k_main(const float* __restrict__ Y,
       const float* __restrict__ W2,
       const float* __restrict__ W_ih,
       const float* __restrict__ b_ih,
       const float* __restrict__ b_hh,
       const float* __restrict__ fcW,
       const float* __restrict__ fcb,
       const float* __restrict__ fcfW,
       const float* __restrict__ fcfb,
       float* __restrict__ out) {
    __shared__ ull   saw[NB * HZ];     // (a_f, w2_f) per row  8 KB
    __shared__ float sdA[NB * HZ];     // d ping                4 KB
    __shared__ float sdB[NB * HZ];     // d pong                4 KB
    __shared__ float sc [NB * HZ];     // c state               4 KB
    __shared__ float sctx[NB * HZ];    // final ctx             4 KB
    __shared__ float sY[NB * Tz];      // Y rows                2 KB
    __shared__ float sy[NB];

    int tid = threadIdx.x, w = tid >> 5, lane = tid & 31;
    int b0 = blockIdx.x * NB;
    int jj = tid & 127, b2 = tid >> 7;   // b2 in {0,1}; rows blr = b2 + 2r

    // init state
    for (int i = tid; i < NB * HZ; i += NT) {
        float w2v = __ldg(&W2[i & 127]);
        saw[i] = pack2(0.0f, w2v);
        sdA[i] = 0.0f;
        sc[i]  = 0.0f;
    }
    for (int i = tid; i < NB * Tz; i += NT)
        sY[i] = __ldg(&Y[(b0 + (i >> 6)) * Tz + (i & 63)]);

    // per-thread constants
    float wih0 = __ldg(&W_ih[jj]),        wih1 = __ldg(&W_ih[jj + 128]);
    float wih2 = __ldg(&W_ih[jj + 256]),  wih3 = __ldg(&W_ih[jj + 384]);
    float bia0 = __ldg(&b_ih[jj])       + __ldg(&b_hh[jj]);
    float bia1 = __ldg(&b_ih[jj + 128]) + __ldg(&b_hh[jj + 128]);
    float bia2 = __ldg(&b_ih[jj + 256]) + __ldg(&b_hh[jj + 256]);
    float bia3 = __ldg(&b_ih[jj + 384]) + __ldg(&b_hh[jj + 384]);
    float4 fw4 = *(const float4*)&fcW[4 * lane];   // fcW[4l..4l+3]
    float fwy = __ldg(&fcW[HZ]), fb0 = __ldg(&fcb[0]);

    int bl = w;                     // warp w owns batch row bl
    int b  = b0 + bl;
    const unsigned* pT = (const unsigned*)g_sPT + (size_t)b * (FZ * 32);
    const ull* Hb4 = (const ull*)(g_Hh + (size_t)b * Tz * HZ);   // 32 ull per t

    float* sdP = sdA;  // read buffer (d_t)
    float* sdN = sdB;  // write buffer (d_{t+1})
    __syncthreads();

    for (int step = 0; step < Tz; ++step) {
        // ================= phase 1 (warp-local): e, softmax, ctx, y ========
        float s0 = 0.0f, s1 = 0.0f;
        const ull* sawr = &saw[bl * HZ];
#pragma unroll 4
        for (int f = 0; f < FZ; ++f) {
            unsigned vv = __ldcs(&pT[f * 32 + lane]);
            __half2 vh = *(__half2*)&vv;
            float2 v = __half22float2(vh);
            ull aw = sawr[f];
            float af = lo2(aw), wf = hi2(aw);
            s0 += tanh_approx(v.x + af) * wf;
            s1 += tanh_approx(v.y + af) * wf;
        }
        float m = fmaxf(s0, s1);
#pragma unroll
        for (int o = 16; o > 0; o >>= 1) m = fmaxf(m, __shfl_xor_sync(0xffffffffu, m, o));
        float e0 = __expf(s0 - m), e1 = __expf(s1 - m);
        float ssum = wred(e0 + e1);
        float inv = __fdividef(1.0f, ssum);
        float beta0 = e0 * inv, beta1 = e1 * inv;

        // ctx: lane owns f = 4*lane .. 4*lane+3
        float c0 = 0.0f, c1 = 0.0f, c2 = 0.0f, c3 = 0.0f;
#pragma unroll 4
        for (int t = 0; t < Tz; t += 2) {
            float bbA = __shfl_sync(0xffffffffu, beta0, t >> 1);
            float bbB = __shfl_sync(0xffffffffu, beta1, t >> 1);
            ull hvA = __ldcs(&Hb4[t * 32 + lane]);
            ull hvB = __ldcs(&Hb4[(t + 1) * 32 + lane]);
            __half2 haA = *(__half2*)&hvA; unsigned hiA = (unsigned)(hvA >> 32);
            __half2 hbA = *(__half2*)&hiA;
            __half2 haB = *(__half2*)&hvB; unsigned hiB = (unsigned)(hvB >> 32);
            __half2 hbB = *(__half2*)&hiB;
            float2 fA0 = __half22float2(haA), fA1 = __half22float2(hbA);
            float2 fB0 = __half22float2(haB), fB1 = __half22float2(hbB);
            c0 += bbA * fA0.x + bbB * fB0.x;
            c1 += bbA * fA0.y + bbB * fB0.y;
            c2 += bbA * fA1.x + bbB * fB1.x;
            c3 += bbA * fA1.y + bbB * fB1.y;
        }
        if (step == Tz - 1) {
            *(float4*)&sctx[bl * HZ + 4 * lane] = make_float4(c0, c1, c2, c3);
        }
        float sdot = c0 * fw4.x + c1 * fw4.y + c2 * fw4.z + c3 * fw4.w;
        sdot = wred(sdot);
        if (lane == 0)
            sy[bl] = sdot + sY[bl * Tz + step] * fwy + fb0;

        __syncthreads();   // A: sy ready; all reads of saw done

        // ================= gates GEMV =====================================
        ull ai[4], af_[4], ag[4], ao[4];
#pragma unroll
        for (int r = 0; r < 4; ++r) { ai[r] = 0; af_[4 - 1 - r] = 0; ag[r] = 0; ao[r] = 0; }
#pragma unroll 2
        for (int hq = 0; hq < 32; ++hq) {       // h = 4*hq
            ulonglong2 wa0 = __ldg(&g_WA[(2 * hq)     * 128 + jj]);
            ulonglong2 wa1 = __ldg(&g_WA[(2 * hq + 1) * 128 + jj]);
            ulonglong2 wb0 = __ldg(&g_WB[(2 * hq)     * 128 + jj]);
            ulonglong2 wb1 = __ldg(&g_WB[(2 * hq + 1) * 128 + jj]);
#pragma unroll
            for (int r = 0; r < 4; ++r) {
                int blr = b2 + 2 * r;
                ulonglong2 dd = *(const ulonglong2*)&sdP[blr * HZ + 4 * hq];
                ffma2(ai[r], dd.x, wa0.x);
                ffma2(af_[r], dd.x, wa0.y);
                ffma2(ag[r], dd.x, wb0.x);
                ffma2(ao[r], dd.x, wb0.y);
                ffma2(ai[r], dd.y, wa1.x);
                ffma2(af_[r], dd.y, wa1.y);
                ffma2(ag[r], dd.y, wb1.x);
                ffma2(ao[r], dd.y, wb1.y);
            }
        }

        // ================= LSTM pointwise =================================
#pragma unroll
        for (int r = 0; r < 4; ++r) {
            int blr = b2 + 2 * r;
            float yt = sy[blr];
            float gi = hsum(ai[r])  + yt * wih0 + bia0;
            float gf = hsum(af_[r]) + yt * wih1 + bia1;
            float gg = hsum(ag[r])  + yt * wih2 + bia2;
            float go = hsum(ao[r])  + yt * wih3 + bia3;
            float cold = sc[blr * HZ + jj];
            float cn = sigm(gf) * cold + sigm(gi) * fast_tanh(gg);
            float dn = sigm(go) * fast_tanh(cn);
            sc[blr * HZ + jj]  = cn;
            sdN[blr * HZ + jj] = dn;
        }
        __syncthreads();   // B: sdN, sc ready

        // ================= a_next = [d,c] @ W1_dc ==========================
        ull aa[4];
#pragma unroll
        for (int r = 0; r < 4; ++r) aa[r] = 0;
#pragma unroll 2
        for (int hq = 0; hq < 32; ++hq) {
            ulonglong2 w0 = __ldg(&g_W1P[(2 * hq)     * 128 + jj]);
            ulonglong2 w1 = __ldg(&g_W1P[(2 * hq + 1) * 128 + jj]);
#pragma unroll
            for (int r = 0; r < 4; ++r) {
                int blr = b2 + 2 * r;
                ulonglong2 dd = *(const ulonglong2*)&sdN[blr * HZ + 4 * hq];
                ulonglong2 cc = *(const ulonglong2*)&sc[blr * HZ + 4 * hq];
                ffma2(aa[r], dd.x, w0.x);
                ffma2(aa[r], cc.x, w0.y);
                ffma2(aa[r], dd.y, w1.x);
                ffma2(aa[r], cc.y, w1.y);
            }
        }
#pragma unroll
        for (int r = 0; r < 4; ++r) {
            int blr = b2 + 2 * r;
            float w2v = __ldg(&W2[jj]);
            saw[blr * HZ + jj] = pack2(hsum(aa[r]), w2v);
        }
        // swap ping-pong
        float* tmp = sdP; sdP = sdN; sdN = tmp;
        __syncthreads();   // C: saw, sdP ready for next step
    }

    // ---- final: out[b] = d.fcf[0:128] + ctx.fcf[128:256] + fcfb ----
    float s = 0.0f;
#pragma unroll
    for (int k = 0; k < 4; ++k) {
        int f = lane + 32 * k;
        s += sdP[bl * HZ + f] * __ldg(&fcfW[f]) + sctx[bl * HZ + f] * __ldg(&fcfW[128 + f]);
    }
    s = wred(s);
    if (lane == 0) out[b] = s + __ldg(&fcfb[0]);
}

extern "C" void kernel_launch(void* const* d_in, const int* in_sizes, int n_in,
                              void* d_out, int out_size) {
    (void)in_sizes; (void)n_in; (void)out_size;
    const float* H    = (const float*)d_in[0];
    const float* Y    = (const float*)d_in[1];
    const float* W1   = (const float*)d_in[2];
    const float* b1   = (const float*)d_in[3];
    const float* W2   = (const float*)d_in[4];
    // d_in[5] = attn_b2: cancels in softmax.
    const float* W_ih = (const float*)d_in[6];
    const float* Whh  = (const float*)d_in[7];
    const float* b_ih = (const float*)d_in[8];
    const float* b_hh = (const float*)d_in[9];
    const float* fcW  = (const float*)d_in[10];
    const float* fcb  = (const float*)d_in[11];
    const float* fcfW = (const float*)d_in[12];
    const float* fcfb = (const float*)d_in[13];
    float* out = (float*)d_out;

    static int configured = 0;
    if (!configured) {
        cudaFuncSetAttribute(k_init, cudaFuncAttributeMaxDynamicSharedMemorySize, SMEM_INIT);
        configured = 1;
    }

    k_tr<<<dim3(4, 16), dim3(32, 8)>>>(Whh);
    k_pack<<<96, 256>>>(W1);
    k_init<<<Bz, 256, SMEM_INIT>>>(H, W1, b1);
    k_main<<<Bz / NB, NT>>>(Y, W2, W_ih, b_ih, b_hh, fcW, fcb, fcfW, fcfb, out);
}

// round 5
// speedup vs baseline: 1.1279x; 1.1279x over previous
#include <cuda_runtime.h>
#include <cuda_fp16.h>
#include <math.h>

#define Bz   2048
#define Tz   64
#define HZ   128   // HID
#define FZ   128   // FEAT
#define NB   16    // batch rows per persistent CTA
#define NT   512   // threads per CTA

typedef unsigned long long ull;

// ---------------- scratch (static device globals) ----------------
__device__ unsigned   g_sPT[(size_t)Bz * 4096];   // [b][fp*64 + lane*2 + par] half2(t0,t1) (32 MB)
__device__ ulonglong2 g_HhP[(size_t)Bz * 1024];   // [b][tp*32+lane] x: 4f@tEven, y: 4f@tOdd (32 MB)
__device__ float      g_WhT[HZ * 4 * HZ];         // Whh^T [128h][512j]
__device__ ulonglong2 g_fW[3 * 4096];             // fp16 weight tables (192 KB)
//   table0 [hq][jj]: x = wi[h0..h3] halves, y = wf[h0..h3]
//   table1 [hq][jj]: x = wg[h0..h3],        y = wo[h0..h3]
//   table2 [hq][jj]: x = w1d[h0..h3],       y = w1c[h0..h3]

// ---------------- helpers ----------------
__device__ __forceinline__ float wred(float v) {
#pragma unroll
    for (int o = 16; o > 0; o >>= 1) v += __shfl_xor_sync(0xffffffffu, v, o);
    return v;
}
__device__ __forceinline__ float fast_tanh(float x) {
    float e = __expf(2.0f * x);
    return 1.0f - __fdividef(2.0f, e + 1.0f);
}
__device__ __forceinline__ float tanh_approx(float x) {
    float r; asm("tanh.approx.f32 %0, %1;" : "=f"(r) : "f"(x)); return r;
}
__device__ __forceinline__ float sigm(float x) {
    return __fdividef(1.0f, 1.0f + __expf(-x));
}
__device__ __forceinline__ ull pack2(float a, float b) {
    return (ull)__float_as_uint(a) | ((ull)__float_as_uint(b) << 32);
}
__device__ __forceinline__ float lo2(ull v) { return __uint_as_float((unsigned)v); }
__device__ __forceinline__ float hi2(ull v) { return __uint_as_float((unsigned)(v >> 32)); }
__device__ __forceinline__ void ffma2(ull &acc, ull a, ull b) {
    asm("fma.rn.f32x2 %0, %1, %2, %0;" : "+l"(acc) : "l"(a), "l"(b));
}
__device__ __forceinline__ float hsum(ull v) { return lo2(v) + hi2(v); }
__device__ __forceinline__ ull h2f2(__half2 h) {   // half2 -> f32x2 register pair
    float2 f = __half22float2(h);
    return pack2(f.x, f.y);
}

// ---------------------------------------------------------------------------
// k_tr: tiled transpose Whh [512,128] -> g_WhT [128,512]
// ---------------------------------------------------------------------------
__global__ void k_tr(const float* __restrict__ Whh) {
    __shared__ float tile[32][33];
    int tx = threadIdx.x, ty = threadIdx.y;
    int x = blockIdx.x * 32 + tx;
    int y = blockIdx.y * 32 + ty;
#pragma unroll
    for (int k = 0; k < 32; k += 8)
        tile[ty + k][tx] = Whh[(y + k) * HZ + x];
    __syncthreads();
    int x2 = blockIdx.y * 32 + tx;
    int y2 = blockIdx.x * 32 + ty;
#pragma unroll
    for (int k = 0; k < 32; k += 8)
        g_WhT[(y2 + k) * 512 + x2] = tile[tx][ty + k];
}

// ---------------------------------------------------------------------------
// k_pack: build fp16 packed weight tables (12288 entries)
// ---------------------------------------------------------------------------
__global__ void k_pack(const float* __restrict__ W1) {
    int idx = blockIdx.x * 256 + threadIdx.x;   // 0..12287
    int table = idx >> 12;
    int e = idx & 4095;
    int hq = e >> 7, jj = e & 127;
    union { ull u; __half h[4]; } ux, uy;
#pragma unroll
    for (int e2 = 0; e2 < 4; ++e2) {
        int h = 4 * hq + e2;
        float x, y;
        if (table == 0)      { x = g_WhT[h * 512 + jj];        y = g_WhT[h * 512 + 128 + jj]; }
        else if (table == 1) { x = g_WhT[h * 512 + 256 + jj];  y = g_WhT[h * 512 + 384 + jj]; }
        else                 { x = __ldg(&W1[h * FZ + jj]);    y = __ldg(&W1[(128 + h) * FZ + jj]); }
        ux.h[e2] = __float2half(x);
        uy.h[e2] = __float2half(y);
    }
    g_fW[idx] = make_ulonglong2(ux.u, uy.u);
}

// ---------------------------------------------------------------------------
// k_init: sP GEMM -> g_sPT (new layout), fp16 H -> g_HhP (new layout)
// ---------------------------------------------------------------------------
#define SMEM_INIT (HZ * 68 * 4 + 32 * 129 * 4)
__global__ void k_init(const float* __restrict__ H,
                       const float* __restrict__ W1,
                       const float* __restrict__ b1) {
    extern __shared__ char smraw[];
    float*    sHT    = (float*)smraw;                    // [128h][68pad]
    unsigned* sStage = (unsigned*)(smraw + HZ * 68 * 4); // [32tp][129pad] half2(t0,t1)
    int b = blockIdx.x, tid = threadIdx.x;
    const float* Hb = H + (size_t)b * Tz * HZ;
    for (int i = tid; i < Tz * HZ; i += 256) {
        int t = i >> 7, h = i & 127;
        sHT[h * 68 + t] = Hb[i];
    }
    __syncthreads();

    int f = tid & 127, half_id = tid >> 7;
    float bias = __ldg(&b1[f]);
    ull acc[16];
#pragma unroll
    for (int k = 0; k < 16; ++k) acc[k] = pack2(bias, bias);

#pragma unroll 2
    for (int h = 0; h < HZ; ++h) {
        float w = __ldg(&W1[(256 + h) * FZ + f]);
        ull ww = pack2(w, w);
        const ull* row = (const ull*)&sHT[h * 68];
#pragma unroll
        for (int k = 0; k < 16; ++k)
            ffma2(acc[k], row[half_id * 16 + k], ww);
    }
#pragma unroll
    for (int k = 0; k < 16; ++k) {
        int tp = half_id * 16 + k;
        __half2 hv = __floats2half2_rn(lo2(acc[k]), hi2(acc[k]));
        sStage[tp * 129 + f] = *(unsigned*)&hv;
    }
    __syncthreads();

    // g_sPT: idx = fp*64 + ln*2 + par  -> sStage[ln][2*fp+par]
    unsigned* dst = g_sPT + (size_t)b * 4096;
    for (int i = tid; i < 4096; i += 256) {
        int par = i & 1, ln = (i >> 1) & 31, fp = i >> 6;
        dst[i] = sStage[ln * 129 + 2 * fp + par];
    }
    // g_HhP: [tp*32+lane] x = halves(f=4lane+e)@t=2tp, y = @t=2tp+1
    ulonglong2* hdst = g_HhP + (size_t)b * 1024;
    for (int i = tid; i < 1024; i += 256) {
        int tp = i >> 5, lane = i & 31;
        union { ull u; __half h[4]; } ux, uy;
#pragma unroll
        for (int e = 0; e < 4; ++e) {
            int ff = 4 * lane + e;
            ux.h[e] = __float2half(sHT[ff * 68 + 2 * tp]);
            uy.h[e] = __float2half(sHT[ff * 68 + 2 * tp + 1]);
        }
        hdst[i] = make_ulonglong2(ux.u, uy.u);
    }
}

// ---------------------------------------------------------------------------
// k_main: persistent scan, weights resident in SMEM.
// Grid 128 CTAs x 512 threads; CTA owns NB=16 rows; 1 CTA/SM.
// ---------------------------------------------------------------------------
#define SMEM_MAIN (196608 + 4 * 8192 + 512 + 64)
__global__ void __launch_bounds__(NT, 1)
k_main(const float* __restrict__ Y,
       const float* __restrict__ W2,
       const float* __restrict__ W_ih,
       const float* __restrict__ b_ih,
       const float* __restrict__ b_hh,
       const float* __restrict__ fcW,
       const float* __restrict__ fcb,
       const float* __restrict__ fcfW,
       const float* __restrict__ fcfb,
       float* __restrict__ out) {
    extern __shared__ char smraw[];
    ulonglong2* swGa = (ulonglong2*)smraw;          // [32hq][128jj] (wi|wf)  64 KB
    ulonglong2* swGb = swGa + 4096;                 // (wg|wo)               64 KB
    ulonglong2* swA  = swGb + 4096;                 // (w1d|w1c)             64 KB
    float* sa  = (float*)(smraw + 196608);          // [16][128] a           8 KB
    float* sdA = sa  + 2048;                        // d ping                8 KB
    float* sdB = sdA + 2048;                        // d pong                8 KB
    float* sc  = sdB + 2048;                        // c                     8 KB
    float* sw2 = sc  + 2048;                        // [128]
    float* sy  = sw2 + 128;                         // [16]

    int tid = threadIdx.x, w = tid >> 5, lane = tid & 31;
    int b0 = blockIdx.x * NB;
    int jj = tid & 127, q = tid >> 7;   // rows blr = q + 4r

    // ---- load weight tables into smem (once) ----
    for (int i = tid; i < 12288; i += NT)
        ((ulonglong2*)smraw)[i] = g_fW[i];
    for (int i = tid; i < NB * HZ; i += NT) { sa[i] = 0.0f; sdA[i] = 0.0f; sc[i] = 0.0f; }
    if (tid < FZ) sw2[tid] = __ldg(&W2[tid]);

    // per-thread constants
    float wih0 = __ldg(&W_ih[jj]),        wih1 = __ldg(&W_ih[jj + 128]);
    float wih2 = __ldg(&W_ih[jj + 256]),  wih3 = __ldg(&W_ih[jj + 384]);
    float bia0 = __ldg(&b_ih[jj])       + __ldg(&b_hh[jj]);
    float bia1 = __ldg(&b_ih[jj + 128]) + __ldg(&b_hh[jj + 128]);
    float bia2 = __ldg(&b_ih[jj + 256]) + __ldg(&b_hh[jj + 256]);
    float bia3 = __ldg(&b_ih[jj + 384]) + __ldg(&b_hh[jj + 384]);
    float4 fw4 = *(const float4*)&fcW[4 * lane];
    float fwy = __ldg(&fcW[HZ]), fb0 = __ldg(&fcb[0]);

    int bl = w;                       // warp w owns batch row bl (16 warps, 16 rows)
    int b  = b0 + bl;
    const uint2* pT       = (const uint2*)(g_sPT + (size_t)b * 4096);
    const ulonglong2* HbP = g_HhP + (size_t)b * 1024;

    float* sdP = sdA;
    float* sdN = sdB;
    float cf0 = 0.f, cf1 = 0.f, cf2 = 0.f, cf3 = 0.f;   // final ctx registers
    __syncthreads();

    for (int step = 0; step < Tz; ++step) {
        // ============ phase 1 (warp-local): e, softmax, ctx, y_tilde ======
        float s0 = 0.0f, s1 = 0.0f;
        const float* sar = &sa[bl * HZ];
#pragma unroll 4
        for (int fp = 0; fp < 64; ++fp) {
            uint2 pv = __ldcs(&pT[fp * 32 + lane]);
            float2 af = *(const float2*)&sar[2 * fp];
            float2 wf = *(const float2*)&sw2[2 * fp];
            __half2 h0 = *(__half2*)&pv.x, h1 = *(__half2*)&pv.y;
            float2 v0 = __half22float2(h0), v1 = __half22float2(h1);
            s0 += tanh_approx(v0.x + af.x) * wf.x + tanh_approx(v1.x + af.y) * wf.y;
            s1 += tanh_approx(v0.y + af.x) * wf.x + tanh_approx(v1.y + af.y) * wf.y;
        }
        float m = fmaxf(s0, s1);
#pragma unroll
        for (int o = 16; o > 0; o >>= 1) m = fmaxf(m, __shfl_xor_sync(0xffffffffu, m, o));
        float e0 = __expf(s0 - m), e1 = __expf(s1 - m);
        float ssum = wred(e0 + e1);
        float inv = __fdividef(1.0f, ssum);
        float beta0 = e0 * inv, beta1 = e1 * inv;

        // ctx: lane owns f = 4*lane..4*lane+3
        float c0 = 0.f, c1 = 0.f, c2 = 0.f, c3 = 0.f;
#pragma unroll 4
        for (int tp = 0; tp < 32; ++tp) {
            float bbA = __shfl_sync(0xffffffffu, beta0, tp);
            float bbB = __shfl_sync(0xffffffffu, beta1, tp);
            ulonglong2 hv = __ldcs(&HbP[tp * 32 + lane]);
            __half2* hh = (__half2*)&hv;
            float2 a0 = __half22float2(hh[0]), a1 = __half22float2(hh[1]);
            float2 g0 = __half22float2(hh[2]), g1 = __half22float2(hh[3]);
            c0 += bbA * a0.x + bbB * g0.x;
            c1 += bbA * a0.y + bbB * g0.y;
            c2 += bbA * a1.x + bbB * g1.x;
            c3 += bbA * a1.y + bbB * g1.y;
        }
        if (step == Tz - 1) { cf0 = c0; cf1 = c1; cf2 = c2; cf3 = c3; }
        float sdot = c0 * fw4.x + c1 * fw4.y + c2 * fw4.z + c3 * fw4.w;
        sdot = wred(sdot);
        if (lane == 0)
            sy[bl] = sdot + __ldg(&Y[b * Tz + step]) * fwy + fb0;

        __syncthreads();   // A: sy ready; sa reads done

        // ============ gates GEMV (weights from smem, fp16) ================
        ull ai[4], af_[4], ag[4], ao[4];
#pragma unroll
        for (int r = 0; r < 4; ++r) { ai[r] = 0; af_[r] = 0; ag[r] = 0; ao[r] = 0; }
#pragma unroll 2
        for (int hq = 0; hq < 32; ++hq) {
            ulonglong2 wa = swGa[hq * 128 + jj];
            ulonglong2 wb = swGb[hq * 128 + jj];
            __half2* ha = (__half2*)&wa;
            __half2* hb = (__half2*)&wb;
            ull wi01 = h2f2(ha[0]), wi23 = h2f2(ha[1]);
            ull wf01 = h2f2(ha[2]), wf23 = h2f2(ha[3]);
            ull wg01 = h2f2(hb[0]), wg23 = h2f2(hb[1]);
            ull wo01 = h2f2(hb[2]), wo23 = h2f2(hb[3]);
#pragma unroll
            for (int r = 0; r < 4; ++r) {
                int blr = q + 4 * r;
                float4 dd = *(const float4*)&sdP[blr * HZ + 4 * hq];  // broadcast
                ull d01 = pack2(dd.x, dd.y), d23 = pack2(dd.z, dd.w);
                ffma2(ai[r],  d01, wi01); ffma2(ai[r],  d23, wi23);
                ffma2(af_[r], d01, wf01); ffma2(af_[r], d23, wf23);
                ffma2(ag[r],  d01, wg01); ffma2(ag[r],  d23, wg23);
                ffma2(ao[r],  d01, wo01); ffma2(ao[r],  d23, wo23);
            }
        }

        // ============ LSTM pointwise ======================================
#pragma unroll
        for (int r = 0; r < 4; ++r) {
            int blr = q + 4 * r;
            float yt = sy[blr];
            float gi = hsum(ai[r])  + yt * wih0 + bia0;
            float gf = hsum(af_[r]) + yt * wih1 + bia1;
            float gg = hsum(ag[r])  + yt * wih2 + bia2;
            float go = hsum(ao[r])  + yt * wih3 + bia3;
            float cold = sc[blr * HZ + jj];
            float cn = sigm(gf) * cold + sigm(gi) * fast_tanh(gg);
            float dn = sigm(go) * fast_tanh(cn);
            sc[blr * HZ + jj]  = cn;
            sdN[blr * HZ + jj] = dn;
        }
        __syncthreads();   // B: sdN, sc ready

        // ============ a_next = [d,c] @ W1_dc ==============================
        ull aa[4];
#pragma unroll
        for (int r = 0; r < 4; ++r) aa[r] = 0;
#pragma unroll 2
        for (int hq = 0; hq < 32; ++hq) {
            ulonglong2 wv = swA[hq * 128 + jj];
            __half2* hw = (__half2*)&wv;
            ull wd01 = h2f2(hw[0]), wd23 = h2f2(hw[1]);
            ull wc01 = h2f2(hw[2]), wc23 = h2f2(hw[3]);
#pragma unroll
            for (int r = 0; r < 4; ++r) {
                int blr = q + 4 * r;
                float4 dd = *(const float4*)&sdN[blr * HZ + 4 * hq];  // broadcast
                float4 cc = *(const float4*)&sc[blr * HZ + 4 * hq];
                ffma2(aa[r], pack2(dd.x, dd.y), wd01);
                ffma2(aa[r], pack2(dd.z, dd.w), wd23);
                ffma2(aa[r], pack2(cc.x, cc.y), wc01);
                ffma2(aa[r], pack2(cc.z, cc.w), wc23);
            }
        }
#pragma unroll
        for (int r = 0; r < 4; ++r)
            sa[(q + 4 * r) * HZ + jj] = hsum(aa[r]);

        float* tmp = sdP; sdP = sdN; sdN = tmp;
        __syncthreads();   // C: sa, sdP ready for next step
    }

    // ---- final: out[b] = d.fcf[0:128] + ctx.fcf[128:256] + fcfb ----
    float4 fa = *(const float4*)&fcfW[4 * lane];
    float4 fbv = *(const float4*)&fcfW[128 + 4 * lane];
    float4 dd = *(const float4*)&sdP[bl * HZ + 4 * lane];
    float s = dd.x * fa.x + dd.y * fa.y + dd.z * fa.z + dd.w * fa.w
            + cf0 * fbv.x + cf1 * fbv.y + cf2 * fbv.z + cf3 * fbv.w;
    s = wred(s);
    if (lane == 0) out[b] = s + __ldg(&fcfb[0]);
}

extern "C" void kernel_launch(void* const* d_in, const int* in_sizes, int n_in,
                              void* d_out, int out_size) {
    (void)in_sizes; (void)n_in; (void)out_size;
    const float* H    = (const float*)d_in[0];
    const float* Y    = (const float*)d_in[1];
    const float* W1   = (const float*)d_in[2];
    const float* b1   = (const float*)d_in[3];
    const float* W2   = (const float*)d_in[4];
    // d_in[5] = attn_b2: cancels in softmax.
    const float* W_ih = (const float*)d_in[6];
    const float* Whh  = (const float*)d_in[7];
    const float* b_ih = (const float*)d_in[8];
    const float* b_hh = (const float*)d_in[9];
    const float* fcW  = (const float*)d_in[10];
    const float* fcb  = (const float*)d_in[11];
    const float* fcfW = (const float*)d_in[12];
    const float* fcfb = (const float*)d_in[13];
    float* out = (float*)d_out;

    static int configured = 0;
    if (!configured) {
        cudaFuncSetAttribute(k_init, cudaFuncAttributeMaxDynamicSharedMemorySize, SMEM_INIT);
        cudaFuncSetAttribute(k_main, cudaFuncAttributeMaxDynamicSharedMemorySize, SMEM_MAIN);
        configured = 1;
    }

    k_tr<<<dim3(4, 16), dim3(32, 8)>>>(Whh);
    k_pack<<<48, 256>>>(W1);
    k_init<<<Bz, 256, SMEM_INIT>>>(H, W1, b1);
    k_main<<<Bz / NB, NT, SMEM_MAIN>>>(Y, W2, W_ih, b_ih, b_hh, fcW, fcb, fcfW, fcfb, out);
}

// round 6
// speedup vs baseline: 1.6968x; 1.5044x over previous
#include <cuda_runtime.h>
#include <cuda_fp16.h>
#include <math.h>

#define Bz   2048
#define Tz   64
#define HZ   128   // HID
#define FZ   128   // FEAT
#define NB   16    // batch rows per persistent CTA
#define NT   512   // threads per CTA

typedef unsigned long long ull;

// ---------------- scratch (static device globals) ----------------
__device__ unsigned   g_sPT[(size_t)Bz * 4096];   // [b][fp*64+ln*2+par] half2(t0,t1) (32 MB)
__device__ ulonglong2 g_HhP[(size_t)Bz * 1024];   // [b][tp*32+lane] fp16 H packed (32 MB)
__device__ float      g_WhT[HZ * 4 * HZ];         // Whh^T [128h][512j]
__device__ ulonglong2 g_fW[3 * 4096];             // fp16 weight tables (192 KB)
__device__ __half     g_hfc[(size_t)Bz * Tz];     // H[b,t]·fcW  (256 KB)

// ---------------- helpers ----------------
__device__ __forceinline__ float wred(float v) {
#pragma unroll
    for (int o = 16; o > 0; o >>= 1) v += __shfl_xor_sync(0xffffffffu, v, o);
    return v;
}
__device__ __forceinline__ float fast_tanh(float x) {
    float e = __expf(2.0f * x);
    return 1.0f - __fdividef(2.0f, e + 1.0f);
}
__device__ __forceinline__ float tanh_approx(float x) {
    float r; asm("tanh.approx.f32 %0, %1;" : "=f"(r) : "f"(x)); return r;
}
__device__ __forceinline__ float sigm(float x) {
    return __fdividef(1.0f, 1.0f + __expf(-x));
}
__device__ __forceinline__ ull pack2(float a, float b) {
    return (ull)__float_as_uint(a) | ((ull)__float_as_uint(b) << 32);
}
__device__ __forceinline__ float lo2(ull v) { return __uint_as_float((unsigned)v); }
__device__ __forceinline__ float hi2(ull v) { return __uint_as_float((unsigned)(v >> 32)); }
__device__ __forceinline__ void ffma2(ull &acc, ull a, ull b) {
    asm("fma.rn.f32x2 %0, %1, %2, %0;" : "+l"(acc) : "l"(a), "l"(b));
}
__device__ __forceinline__ float hsum(ull v) { return lo2(v) + hi2(v); }
__device__ __forceinline__ ull h2f2(__half2 h) {
    float2 f = __half22float2(h);
    return pack2(f.x, f.y);
}

// ---------------------------------------------------------------------------
// k_tr: tiled transpose Whh [512,128] -> g_WhT [128,512]
// ---------------------------------------------------------------------------
__global__ void k_tr(const float* __restrict__ Whh) {
    __shared__ float tile[32][33];
    int tx = threadIdx.x, ty = threadIdx.y;
    int x = blockIdx.x * 32 + tx;
    int y = blockIdx.y * 32 + ty;
#pragma unroll
    for (int k = 0; k < 32; k += 8)
        tile[ty + k][tx] = Whh[(y + k) * HZ + x];
    __syncthreads();
    int x2 = blockIdx.y * 32 + tx;
    int y2 = blockIdx.x * 32 + ty;
#pragma unroll
    for (int k = 0; k < 32; k += 8)
        g_WhT[(y2 + k) * 512 + x2] = tile[tx][ty + k];
}

// ---------------------------------------------------------------------------
// k_pack: build fp16 packed weight tables (12288 entries)
// ---------------------------------------------------------------------------
__global__ void k_pack(const float* __restrict__ W1) {
    int idx = blockIdx.x * 256 + threadIdx.x;   // 0..12287
    int table = idx >> 12;
    int e = idx & 4095;
    int hq = e >> 7, jj = e & 127;
    union { ull u; __half h[4]; } ux, uy;
#pragma unroll
    for (int e2 = 0; e2 < 4; ++e2) {
        int h = 4 * hq + e2;
        float x, y;
        if (table == 0)      { x = g_WhT[h * 512 + jj];        y = g_WhT[h * 512 + 128 + jj]; }
        else if (table == 1) { x = g_WhT[h * 512 + 256 + jj];  y = g_WhT[h * 512 + 384 + jj]; }
        else                 { x = __ldg(&W1[h * FZ + jj]);    y = __ldg(&W1[(128 + h) * FZ + jj]); }
        ux.h[e2] = __float2half(x);
        uy.h[e2] = __float2half(y);
    }
    g_fW[idx] = make_ulonglong2(ux.u, uy.u);
}

// ---------------------------------------------------------------------------
// k_init: sP GEMM -> g_sPT; fp16 H -> g_HhP; hfc = H·fcW -> g_hfc
// ---------------------------------------------------------------------------
#define SMEM_INIT (HZ * 68 * 4 + 32 * 129 * 4)
__global__ void k_init(const float* __restrict__ H,
                       const float* __restrict__ W1,
                       const float* __restrict__ b1,
                       const float* __restrict__ fcW) {
    extern __shared__ char smraw[];
    float*    sHT    = (float*)smraw;                    // [128h][68pad]
    unsigned* sStage = (unsigned*)(smraw + HZ * 68 * 4); // [32tp][129pad]
    int b = blockIdx.x, tid = threadIdx.x;
    const float* Hb = H + (size_t)b * Tz * HZ;
    for (int i = tid; i < Tz * HZ; i += 256) {
        int t = i >> 7, h = i & 127;
        sHT[h * 68 + t] = Hb[i];
    }
    __syncthreads();

    // hfc[t] = sum_f H[b,t,f]*fcW[f]
    if (tid < Tz) {
        float acc = 0.0f;
#pragma unroll 4
        for (int f = 0; f < HZ; ++f)
            acc += sHT[f * 68 + tid] * __ldg(&fcW[f]);
        g_hfc[(size_t)b * Tz + tid] = __float2half(acc);
    }

    int f = tid & 127, half_id = tid >> 7;
    float bias = __ldg(&b1[f]);
    ull acc[16];
#pragma unroll
    for (int k = 0; k < 16; ++k) acc[k] = pack2(bias, bias);

#pragma unroll 2
    for (int h = 0; h < HZ; ++h) {
        float w = __ldg(&W1[(256 + h) * FZ + f]);
        ull ww = pack2(w, w);
        const ull* row = (const ull*)&sHT[h * 68];
#pragma unroll
        for (int k = 0; k < 16; ++k)
            ffma2(acc[k], row[half_id * 16 + k], ww);
    }
#pragma unroll
    for (int k = 0; k < 16; ++k) {
        int tp = half_id * 16 + k;
        __half2 hv = __floats2half2_rn(lo2(acc[k]), hi2(acc[k]));
        sStage[tp * 129 + f] = *(unsigned*)&hv;
    }
    __syncthreads();

    unsigned* dst = g_sPT + (size_t)b * 4096;
    for (int i = tid; i < 4096; i += 256) {
        int par = i & 1, ln = (i >> 1) & 31, fp = i >> 6;
        dst[i] = sStage[ln * 129 + 2 * fp + par];
    }
    ulonglong2* hdst = g_HhP + (size_t)b * 1024;
    for (int i = tid; i < 1024; i += 256) {
        int tp = i >> 5, lane = i & 31;
        union { ull u; __half h[4]; } ux, uy;
#pragma unroll
        for (int e = 0; e < 4; ++e) {
            int ff = 4 * lane + e;
            ux.h[e] = __float2half(sHT[ff * 68 + 2 * tp]);
            uy.h[e] = __float2half(sHT[ff * 68 + 2 * tp + 1]);
        }
        hdst[i] = make_ulonglong2(ux.u, uy.u);
    }
}

// ---------------------------------------------------------------------------
// k_main: warp-specialized half-step pipeline.
// Warps 0-7: attention duty (1 row per warp per half-phase).
// Warps 8-15: GEMV duty (gates + pointwise + a_next for 8-row group).
// ---------------------------------------------------------------------------
// smem offsets (bytes)
#define SM_SA    196608                      // float[16*128]  a
#define SM_SD    (SM_SA + 8192)              // float[2][16*128] d ping-pong
#define SM_SC    (SM_SD + 16384)             // float[16*128]  c
#define SM_HFC   (SM_SC + 8192)              // half[16*64]
#define SM_W2    (SM_HFC + 2048)             // float[128]
#define SM_SY    (SM_W2 + 512)               // float[16]
#define SM_CTXD  (SM_SY + 64)                // float[16]
#define SMEM_MAIN (SM_CTXD + 64)             // 232064

// ---- attention for one row (one warp) ----
__device__ __forceinline__ void attn_row(
    int row, int b, int t, int lane, bool do_ctx,
    const float* sa, const float* sw2, const __half2* shfc2,
    float* sy, float* sctxd,
    const float* __restrict__ Y, float fwy, float fb0,
    const float* __restrict__ fcfW)
{
    const uint2* pT = (const uint2*)(g_sPT + (size_t)b * 4096);
    const float* sar = sa + row * HZ;
    float s0 = 0.0f, s1 = 0.0f;
#pragma unroll 8
    for (int fp = 0; fp < 64; ++fp) {
        uint2 pv = __ldcs(&pT[fp * 32 + lane]);
        float2 af = *(const float2*)&sar[2 * fp];
        float2 wf = *(const float2*)&sw2[2 * fp];
        __half2 h0 = *(__half2*)&pv.x, h1 = *(__half2*)&pv.y;
        float2 v0 = __half22float2(h0), v1 = __half22float2(h1);
        s0 += tanh_approx(v0.x + af.x) * wf.x + tanh_approx(v1.x + af.y) * wf.y;
        s1 += tanh_approx(v0.y + af.x) * wf.x + tanh_approx(v1.y + af.y) * wf.y;
    }
    float m = fmaxf(s0, s1);
#pragma unroll
    for (int o = 16; o > 0; o >>= 1) m = fmaxf(m, __shfl_xor_sync(0xffffffffu, m, o));
    float e0 = __expf(s0 - m), e1 = __expf(s1 - m);
    float ssum = wred(e0 + e1);
    float inv = __fdividef(1.0f, ssum);
    float beta0 = e0 * inv, beta1 = e1 * inv;

    // y_tilde via precomputed hfc
    float2 hc = __half22float2(shfc2[row * 32 + lane]);
    float part = beta0 * hc.x + beta1 * hc.y;
    part = wred(part);
    if (lane == 0)
        sy[row] = part + __ldg(&Y[b * Tz + t]) * fwy + fb0;

    if (do_ctx) {   // last step: full context + output-head dot
        const ulonglong2* HbP = g_HhP + (size_t)b * 1024;
        float c0 = 0.f, c1 = 0.f, c2 = 0.f, c3 = 0.f;
#pragma unroll 4
        for (int tp = 0; tp < 32; ++tp) {
            float bbA = __shfl_sync(0xffffffffu, beta0, tp);
            float bbB = __shfl_sync(0xffffffffu, beta1, tp);
            ulonglong2 hv = __ldcs(&HbP[tp * 32 + lane]);
            __half2* hh = (__half2*)&hv;
            float2 a0 = __half22float2(hh[0]), a1 = __half22float2(hh[1]);
            float2 g0 = __half22float2(hh[2]), g1 = __half22float2(hh[3]);
            c0 += bbA * a0.x + bbB * g0.x;
            c1 += bbA * a0.y + bbB * g0.y;
            c2 += bbA * a1.x + bbB * g1.x;
            c3 += bbA * a1.y + bbB * g1.y;
        }
        float4 f2 = *(const float4*)&fcfW[128 + 4 * lane];
        float cd = c0 * f2.x + c1 * f2.y + c2 * f2.z + c3 * f2.w;
        cd = wred(cd);
        if (lane == 0) sctxd[row] = cd;
    }
}

// ---- gates + pointwise + a_next for one 8-row group (warps 8-15) ----
__device__ __forceinline__ void gates_group(
    int base, int t, int jj, int q,
    const ulonglong2* swGa, const ulonglong2* swGb, const ulonglong2* swA,
    float* sd, float* sc, float* sa, const float* sy,
    float wih0, float wih1, float wih2, float wih3,
    float bia0, float bia1, float bia2, float bia3)
{
    float* sdP = sd + (t & 1) * 2048;
    float* sdN = sd + ((t + 1) & 1) * 2048;

    ull ai[4], afx[4], ag[4], ao[4];
#pragma unroll
    for (int r = 0; r < 4; ++r) { ai[r] = 0; afx[r] = 0; ag[r] = 0; ao[r] = 0; }
#pragma unroll 2
    for (int hq = 0; hq < 32; ++hq) {
        ulonglong2 wa = swGa[hq * 128 + jj];
        ulonglong2 wb = swGb[hq * 128 + jj];
        __half2* ha = (__half2*)&wa;
        __half2* hb = (__half2*)&wb;
        ull wi01 = h2f2(ha[0]), wi23 = h2f2(ha[1]);
        ull wf01 = h2f2(ha[2]), wf23 = h2f2(ha[3]);
        ull wg01 = h2f2(hb[0]), wg23 = h2f2(hb[1]);
        ull wo01 = h2f2(hb[2]), wo23 = h2f2(hb[3]);
#pragma unroll
        for (int r = 0; r < 4; ++r) {
            int blr = base + q + 2 * r;
            float4 dd = *(const float4*)&sdP[blr * HZ + 4 * hq];
            ull d01 = pack2(dd.x, dd.y), d23 = pack2(dd.z, dd.w);
            ffma2(ai[r],  d01, wi01); ffma2(ai[r],  d23, wi23);
            ffma2(afx[r], d01, wf01); ffma2(afx[r], d23, wf23);
            ffma2(ag[r],  d01, wg01); ffma2(ag[r],  d23, wg23);
            ffma2(ao[r],  d01, wo01); ffma2(ao[r],  d23, wo23);
        }
    }
#pragma unroll
    for (int r = 0; r < 4; ++r) {
        int blr = base + q + 2 * r;
        float yt = sy[blr];
        float gi = hsum(ai[r])  + yt * wih0 + bia0;
        float gf = hsum(afx[r]) + yt * wih1 + bia1;
        float gg = hsum(ag[r])  + yt * wih2 + bia2;
        float go = hsum(ao[r])  + yt * wih3 + bia3;
        float cold = sc[blr * HZ + jj];
        float cn = sigm(gf) * cold + sigm(gi) * fast_tanh(gg);
        float dn = sigm(go) * fast_tanh(cn);
        sc[blr * HZ + jj]  = cn;
        sdN[blr * HZ + jj] = dn;
    }
    // sync only the 8 gemv warps (256 threads), barrier id 1
    asm volatile("bar.sync 1, 256;" ::: "memory");

    ull aa[4];
#pragma unroll
    for (int r = 0; r < 4; ++r) aa[r] = 0;
#pragma unroll 2
    for (int hq = 0; hq < 32; ++hq) {
        ulonglong2 wv = swA[hq * 128 + jj];
        __half2* hw = (__half2*)&wv;
        ull wd01 = h2f2(hw[0]), wd23 = h2f2(hw[1]);
        ull wc01 = h2f2(hw[2]), wc23 = h2f2(hw[3]);
#pragma unroll
        for (int r = 0; r < 4; ++r) {
            int blr = base + q + 2 * r;
            float4 dd = *(const float4*)&sdN[blr * HZ + 4 * hq];
            float4 cc = *(const float4*)&sc[blr * HZ + 4 * hq];
            ffma2(aa[r], pack2(dd.x, dd.y), wd01);
            ffma2(aa[r], pack2(dd.z, dd.w), wd23);
            ffma2(aa[r], pack2(cc.x, cc.y), wc01);
            ffma2(aa[r], pack2(cc.z, cc.w), wc23);
        }
    }
#pragma unroll
    for (int r = 0; r < 4; ++r)
        sa[(base + q + 2 * r) * HZ + jj] = hsum(aa[r]);
}

__global__ void __launch_bounds__(NT, 1)
k_main(const float* __restrict__ Y,
       const float* __restrict__ W2,
       const float* __restrict__ W_ih,
       const float* __restrict__ b_ih,
       const float* __restrict__ b_hh,
       const float* __restrict__ fcW,
       const float* __restrict__ fcb,
       const float* __restrict__ fcfW,
       const float* __restrict__ fcfb,
       float* __restrict__ out) {
    extern __shared__ char smraw[];
    ulonglong2* swGa = (ulonglong2*)smraw;
    ulonglong2* swGb = swGa + 4096;
    ulonglong2* swA  = swGb + 4096;
    float*   sa    = (float*)(smraw + SM_SA);
    float*   sd    = (float*)(smraw + SM_SD);
    float*   sc    = (float*)(smraw + SM_SC);
    __half2* shfc2 = (__half2*)(smraw + SM_HFC);
    float*   sw2   = (float*)(smraw + SM_W2);
    float*   sy    = (float*)(smraw + SM_SY);
    float*   sctxd = (float*)(smraw + SM_CTXD);

    int tid = threadIdx.x, w = tid >> 5, lane = tid & 31;
    int b0 = blockIdx.x * NB;
    bool is_attn = (tid < 256);

    // one-time loads
    for (int i = tid; i < 12288; i += NT)
        ((ulonglong2*)smraw)[i] = g_fW[i];
    for (int i = tid; i < NB * HZ; i += NT) {
        sa[i] = 0.0f; sd[i] = 0.0f; sc[i] = 0.0f;   // sd ping(0) zeroed
    }
    for (int i = tid; i < NB * Tz / 2; i += NT)
        shfc2[i] = ((const __half2*)g_hfc)[b0 * 32 + i];
    if (tid < FZ) sw2[tid] = __ldg(&W2[tid]);

    // gemv-thread constants
    int tid2 = tid & 255;
    int jj = tid2 & 127, q = tid2 >> 7;
    float wih0 = __ldg(&W_ih[jj]),        wih1 = __ldg(&W_ih[jj + 128]);
    float wih2 = __ldg(&W_ih[jj + 256]),  wih3 = __ldg(&W_ih[jj + 384]);
    float bia0 = __ldg(&b_ih[jj])       + __ldg(&b_hh[jj]);
    float bia1 = __ldg(&b_ih[jj + 128]) + __ldg(&b_hh[jj + 128]);
    float bia2 = __ldg(&b_ih[jj + 256]) + __ldg(&b_hh[jj + 256]);
    float bia3 = __ldg(&b_ih[jj + 384]) + __ldg(&b_hh[jj + 384]);
    // attn-thread constants
    float fwy = __ldg(&fcW[HZ]), fb0 = __ldg(&fcb[0]);

    __syncthreads();

    for (int t = 0; t < Tz; ++t) {
        // ---- HP1: attn A(t) || gates B(t-1) ----
        if (is_attn) {
            attn_row(w, b0 + w, t, lane, t == Tz - 1,
                     sa, sw2, shfc2, sy, sctxd, Y, fwy, fb0, fcfW);
        } else if (t > 0) {
            gates_group(8, t - 1, jj, q, swGa, swGb, swA, sd, sc, sa, sy,
                        wih0, wih1, wih2, wih3, bia0, bia1, bia2, bia3);
        }
        __syncthreads();
        // ---- HP2: attn B(t) || gates A(t) ----
        if (is_attn) {
            attn_row(8 + w, b0 + 8 + w, t, lane, t == Tz - 1,
                     sa, sw2, shfc2, sy, sctxd, Y, fwy, fb0, fcfW);
        } else {
            gates_group(0, t, jj, q, swGa, swGb, swA, sd, sc, sa, sy,
                        wih0, wih1, wih2, wih3, bia0, bia1, bia2, bia3);
        }
        __syncthreads();
    }
    // ---- epilogue: gates B(63) ----
    if (!is_attn) {
        gates_group(8, Tz - 1, jj, q, swGa, swGb, swA, sd, sc, sa, sy,
                    wih0, wih1, wih2, wih3, bia0, bia1, bia2, bia3);
    }
    __syncthreads();

    // ---- final: out[b] = d·fcf[0:128] + ctxd + fcfb ----
    // d after step 64 lives in sd ping buffer (64&1 == 0)
    {
        int row = w;   // 16 warps, 16 rows
        float4 fa = *(const float4*)&fcfW[4 * lane];
        float4 dd = *(const float4*)&sd[row * HZ + 4 * lane];
        float s = dd.x * fa.x + dd.y * fa.y + dd.z * fa.z + dd.w * fa.w;
        s = wred(s);
        if (lane == 0) out[b0 + row] = s + sctxd[row] + __ldg(&fcfb[0]);
    }
}

extern "C" void kernel_launch(void* const* d_in, const int* in_sizes, int n_in,
                              void* d_out, int out_size) {
    (void)in_sizes; (void)n_in; (void)out_size;
    const float* H    = (const float*)d_in[0];
    const float* Y    = (const float*)d_in[1];
    const float* W1   = (const float*)d_in[2];
    const float* b1   = (const float*)d_in[3];
    const float* W2   = (const float*)d_in[4];
    // d_in[5] = attn_b2: cancels in softmax.
    const float* W_ih = (const float*)d_in[6];
    const float* Whh  = (const float*)d_in[7];
    const float* b_ih = (const float*)d_in[8];
    const float* b_hh = (const float*)d_in[9];
    const float* fcW  = (const float*)d_in[10];
    const float* fcb  = (const float*)d_in[11];
    const float* fcfW = (const float*)d_in[12];
    const float* fcfb = (const float*)d_in[13];
    float* out = (float*)d_out;

    static int configured = 0;
    if (!configured) {
        cudaFuncSetAttribute(k_init, cudaFuncAttributeMaxDynamicSharedMemorySize, SMEM_INIT);
        cudaFuncSetAttribute(k_main, cudaFuncAttributeMaxDynamicSharedMemorySize, SMEM_MAIN);
        configured = 1;
    }

    k_tr<<<dim3(4, 16), dim3(32, 8)>>>(Whh);
    k_pack<<<48, 256>>>(W1);
    k_init<<<Bz, 256, SMEM_INIT>>>(H, W1, b1, fcW);
    k_main<<<Bz / NB, NT, SMEM_MAIN>>>(Y, W2, W_ih, b_ih, b_hh, fcW, fcb, fcfW, fcfb, out);
}

// round 7
// speedup vs baseline: 1.7069x; 1.0059x over previous
#include <cuda_runtime.h>
#include <cuda_fp16.h>
#include <math.h>

#define Bz   2048
#define Tz   64
#define HZ   128   // HID
#define FZ   128   // FEAT
#define NB   16    // batch rows per persistent CTA
#define NT   512   // threads per CTA

typedef unsigned long long ull;

// ---------------- scratch (static device globals) ----------------
__device__ unsigned   g_sPT[(size_t)Bz * 4096];   // [b][fp*64+ln*2+par] half2(t0,t1) (32 MB)
__device__ ulonglong2 g_HhP[(size_t)Bz * 1024];   // [b][tp*32+lane] fp16 H packed (32 MB)
__device__ float      g_WhT[HZ * 4 * HZ];         // Whh^T [128h][512j]
__device__ ulonglong2 g_fW[3 * 4096];             // fp16 weight tables (192 KB)
__device__ __half     g_hfc[(size_t)Bz * Tz];     // H[b,t]·fcW  (256 KB)

// ---------------- helpers ----------------
__device__ __forceinline__ float wred(float v) {
#pragma unroll
    for (int o = 16; o > 0; o >>= 1) v += __shfl_xor_sync(0xffffffffu, v, o);
    return v;
}
__device__ __forceinline__ float fast_tanh(float x) {
    float e = __expf(2.0f * x);
    return 1.0f - __fdividef(2.0f, e + 1.0f);
}
__device__ __forceinline__ __half2 htanh2(__half2 x) {
    unsigned xi = *(unsigned*)&x, r;
    asm("tanh.approx.f16x2 %0, %1;" : "=r"(r) : "r"(xi));
    return *(__half2*)&r;
}
__device__ __forceinline__ float sigm(float x) {
    return __fdividef(1.0f, 1.0f + __expf(-x));
}
__device__ __forceinline__ ull pack2(float a, float b) {
    return (ull)__float_as_uint(a) | ((ull)__float_as_uint(b) << 32);
}
__device__ __forceinline__ float lo2(ull v) { return __uint_as_float((unsigned)v); }
__device__ __forceinline__ float hi2(ull v) { return __uint_as_float((unsigned)(v >> 32)); }
__device__ __forceinline__ void ffma2(ull &acc, ull a, ull b) {
    asm("fma.rn.f32x2 %0, %1, %2, %0;" : "+l"(acc) : "l"(a), "l"(b));
}
__device__ __forceinline__ float hsum(ull v) { return lo2(v) + hi2(v); }
__device__ __forceinline__ ull h2f2(__half2 h) {
    float2 f = __half22float2(h);
    return pack2(f.x, f.y);
}

// ---------------------------------------------------------------------------
// k_tr: tiled transpose Whh [512,128] -> g_WhT [128,512]
// ---------------------------------------------------------------------------
__global__ void k_tr(const float* __restrict__ Whh) {
    __shared__ float tile[32][33];
    int tx = threadIdx.x, ty = threadIdx.y;
    int x = blockIdx.x * 32 + tx;
    int y = blockIdx.y * 32 + ty;
#pragma unroll
    for (int k = 0; k < 32; k += 8)
        tile[ty + k][tx] = Whh[(y + k) * HZ + x];
    __syncthreads();
    int x2 = blockIdx.y * 32 + tx;
    int y2 = blockIdx.x * 32 + ty;
#pragma unroll
    for (int k = 0; k < 32; k += 8)
        g_WhT[(y2 + k) * 512 + x2] = tile[tx][ty + k];
}

// ---------------------------------------------------------------------------
// k_pack: build fp16 packed weight tables (12288 entries)
// ---------------------------------------------------------------------------
__global__ void k_pack(const float* __restrict__ W1) {
    int idx = blockIdx.x * 256 + threadIdx.x;   // 0..12287
    int table = idx >> 12;
    int e = idx & 4095;
    int hq = e >> 7, jj = e & 127;
    union { ull u; __half h[4]; } ux, uy;
#pragma unroll
    for (int e2 = 0; e2 < 4; ++e2) {
        int h = 4 * hq + e2;
        float x, y;
        if (table == 0)      { x = g_WhT[h * 512 + jj];        y = g_WhT[h * 512 + 128 + jj]; }
        else if (table == 1) { x = g_WhT[h * 512 + 256 + jj];  y = g_WhT[h * 512 + 384 + jj]; }
        else                 { x = __ldg(&W1[h * FZ + jj]);    y = __ldg(&W1[(128 + h) * FZ + jj]); }
        ux.h[e2] = __float2half(x);
        uy.h[e2] = __float2half(y);
    }
    g_fW[idx] = make_ulonglong2(ux.u, uy.u);
}

// ---------------------------------------------------------------------------
// k_init: sP GEMM -> g_sPT; fp16 H -> g_HhP; hfc = H·fcW -> g_hfc
// ---------------------------------------------------------------------------
#define SMEM_INIT (HZ * 68 * 4 + 32 * 129 * 4)
__global__ void k_init(const float* __restrict__ H,
                       const float* __restrict__ W1,
                       const float* __restrict__ b1,
                       const float* __restrict__ fcW) {
    extern __shared__ char smraw[];
    float*    sHT    = (float*)smraw;                    // [128h][68pad]
    unsigned* sStage = (unsigned*)(smraw + HZ * 68 * 4); // [32tp][129pad]
    int b = blockIdx.x, tid = threadIdx.x;
    const float* Hb = H + (size_t)b * Tz * HZ;
    for (int i = tid; i < Tz * HZ; i += 256) {
        int t = i >> 7, h = i & 127;
        sHT[h * 68 + t] = Hb[i];
    }
    __syncthreads();

    if (tid < Tz) {
        float acc = 0.0f;
#pragma unroll 4
        for (int f = 0; f < HZ; ++f)
            acc += sHT[f * 68 + tid] * __ldg(&fcW[f]);
        g_hfc[(size_t)b * Tz + tid] = __float2half(acc);
    }

    int f = tid & 127, half_id = tid >> 7;
    float bias = __ldg(&b1[f]);
    ull acc[16];
#pragma unroll
    for (int k = 0; k < 16; ++k) acc[k] = pack2(bias, bias);

#pragma unroll 2
    for (int h = 0; h < HZ; ++h) {
        float w = __ldg(&W1[(256 + h) * FZ + f]);
        ull ww = pack2(w, w);
        const ull* row = (const ull*)&sHT[h * 68];
#pragma unroll
        for (int k = 0; k < 16; ++k)
            ffma2(acc[k], row[half_id * 16 + k], ww);
    }
#pragma unroll
    for (int k = 0; k < 16; ++k) {
        int tp = half_id * 16 + k;
        __half2 hv = __floats2half2_rn(lo2(acc[k]), hi2(acc[k]));
        sStage[tp * 129 + f] = *(unsigned*)&hv;
    }
    __syncthreads();

    unsigned* dst = g_sPT + (size_t)b * 4096;
    for (int i = tid; i < 4096; i += 256) {
        int par = i & 1, ln = (i >> 1) & 31, fp = i >> 6;
        dst[i] = sStage[ln * 129 + 2 * fp + par];
    }
    ulonglong2* hdst = g_HhP + (size_t)b * 1024;
    for (int i = tid; i < 1024; i += 256) {
        int tp = i >> 5, lane = i & 31;
        union { ull u; __half h[4]; } ux, uy;
#pragma unroll
        for (int e = 0; e < 4; ++e) {
            int ff = 4 * lane + e;
            ux.h[e] = __float2half(sHT[ff * 68 + 2 * tp]);
            uy.h[e] = __float2half(sHT[ff * 68 + 2 * tp + 1]);
        }
        hdst[i] = make_ulonglong2(ux.u, uy.u);
    }
}

// ---------------------------------------------------------------------------
// k_main: warp-specialized half-step pipeline (attn warps 0-7 / gemv 8-15).
// ---------------------------------------------------------------------------
// smem offsets (bytes past the 192 KB weight region)
#define SM_SA    196608                      // half[16*128]   a (fp16)    4 KB
#define SM_SD    (SM_SA + 4096)              // float[2][16*128] d pp     16 KB
#define SM_SC    (SM_SD + 16384)             // float[16*128]  c           8 KB
#define SM_HFC   (SM_SC + 8192)              // half[16*64]                2 KB
#define SM_W2    (SM_HFC + 2048)             // float[128]
#define SM_SY    (SM_W2 + 512)               // float[16]
#define SM_CTXD  (SM_SY + 64)                // float[16]
#define SMEM_MAIN (SM_CTXD + 64)             // 227968

// ---- attention for one row (one warp) ----
__device__ __forceinline__ void attn_row(
    int row, int b, int t, int lane, bool do_ctx,
    const __half2* sah2, const float* sw2, const __half2* shfc2,
    float* sy, float* sctxd,
    const float* __restrict__ Y, float fwy, float fb0,
    const float* __restrict__ fcfW)
{
    const uint2* pT = (const uint2*)(g_sPT + (size_t)b * 4096);
    const __half2* sar = sah2 + row * 64;
    float s0 = 0.0f, s1 = 0.0f;
#pragma unroll 8
    for (int fp = 0; fp < 64; ++fp) {
        uint2 pv = __ldcs(&pT[fp * 32 + lane]);
        __half2 a01 = sar[fp];                       // (a_f0, a_f1)
        float2 wf = *(const float2*)&sw2[2 * fp];
        __half2 h0 = *(__half2*)&pv.x, h1 = *(__half2*)&pv.y;
        __half2 t0 = htanh2(__hadd2(h0, __half2half2(__low2half(a01))));
        __half2 t1 = htanh2(__hadd2(h1, __half2half2(__high2half(a01))));
        float2 f0 = __half22float2(t0), f1 = __half22float2(t1);
        s0 += f0.x * wf.x + f1.x * wf.y;
        s1 += f0.y * wf.x + f1.y * wf.y;
    }
    float m = fmaxf(s0, s1);
#pragma unroll
    for (int o = 16; o > 0; o >>= 1) m = fmaxf(m, __shfl_xor_sync(0xffffffffu, m, o));
    float e0 = __expf(s0 - m), e1 = __expf(s1 - m);
    float ssum = wred(e0 + e1);
    float inv = __fdividef(1.0f, ssum);
    float beta0 = e0 * inv, beta1 = e1 * inv;

    float2 hc = __half22float2(shfc2[row * 32 + lane]);
    float part = beta0 * hc.x + beta1 * hc.y;
    part = wred(part);
    if (lane == 0)
        sy[row] = part + __ldg(&Y[b * Tz + t]) * fwy + fb0;

    if (do_ctx) {
        const ulonglong2* HbP = g_HhP + (size_t)b * 1024;
        float c0 = 0.f, c1 = 0.f, c2 = 0.f, c3 = 0.f;
#pragma unroll 4
        for (int tp = 0; tp < 32; ++tp) {
            float bbA = __shfl_sync(0xffffffffu, beta0, tp);
            float bbB = __shfl_sync(0xffffffffu, beta1, tp);
            ulonglong2 hv = __ldcs(&HbP[tp * 32 + lane]);
            __half2* hh = (__half2*)&hv;
            float2 a0 = __half22float2(hh[0]), a1 = __half22float2(hh[1]);
            float2 g0 = __half22float2(hh[2]), g1 = __half22float2(hh[3]);
            c0 += bbA * a0.x + bbB * g0.x;
            c1 += bbA * a0.y + bbB * g0.y;
            c2 += bbA * a1.x + bbB * g1.x;
            c3 += bbA * a1.y + bbB * g1.y;
        }
        float4 f2 = *(const float4*)&fcfW[128 + 4 * lane];
        float cd = c0 * f2.x + c1 * f2.y + c2 * f2.z + c3 * f2.w;
        cd = wred(cd);
        if (lane == 0) sctxd[row] = cd;
    }
}

// ---- gates + pointwise + a_next for one 8-row group (warps 8-15) ----
__device__ __forceinline__ void gates_group(
    int base, int t, int jj, int q,
    const ulonglong2* swGa, const ulonglong2* swGb, const ulonglong2* swA,
    float* sd, float* sc, __half* sah, const float* sy,
    float wih0, float wih1, float wih2, float wih3,
    float bia0, float bia1, float bia2, float bia3)
{
    float* sdP = sd + (t & 1) * 2048;
    float* sdN = sd + ((t + 1) & 1) * 2048;

    ull ai[4], afx[4], ag[4], ao[4];
#pragma unroll
    for (int r = 0; r < 4; ++r) { ai[r] = 0; afx[r] = 0; ag[r] = 0; ao[r] = 0; }
#pragma unroll 2
    for (int hq = 0; hq < 32; ++hq) {
        ulonglong2 wa = swGa[hq * 128 + jj];
        ulonglong2 wb = swGb[hq * 128 + jj];
        __half2* ha = (__half2*)&wa;
        __half2* hb = (__half2*)&wb;
        ull wi01 = h2f2(ha[0]), wi23 = h2f2(ha[1]);
        ull wf01 = h2f2(ha[2]), wf23 = h2f2(ha[3]);
        ull wg01 = h2f2(hb[0]), wg23 = h2f2(hb[1]);
        ull wo01 = h2f2(hb[2]), wo23 = h2f2(hb[3]);
#pragma unroll
        for (int r = 0; r < 4; ++r) {
            int blr = base + q + 2 * r;
            float4 dd = *(const float4*)&sdP[blr * HZ + 4 * hq];
            ull d01 = pack2(dd.x, dd.y), d23 = pack2(dd.z, dd.w);
            ffma2(ai[r],  d01, wi01); ffma2(ai[r],  d23, wi23);
            ffma2(afx[r], d01, wf01); ffma2(afx[r], d23, wf23);
            ffma2(ag[r],  d01, wg01); ffma2(ag[r],  d23, wg23);
            ffma2(ao[r],  d01, wo01); ffma2(ao[r],  d23, wo23);
        }
    }
#pragma unroll
    for (int r = 0; r < 4; ++r) {
        int blr = base + q + 2 * r;
        float yt = sy[blr];
        float gi = hsum(ai[r])  + yt * wih0 + bia0;
        float gf = hsum(afx[r]) + yt * wih1 + bia1;
        float gg = hsum(ag[r])  + yt * wih2 + bia2;
        float go = hsum(ao[r])  + yt * wih3 + bia3;
        float cold = sc[blr * HZ + jj];
        float cn = sigm(gf) * cold + sigm(gi) * fast_tanh(gg);
        float dn = sigm(go) * fast_tanh(cn);
        sc[blr * HZ + jj]  = cn;
        sdN[blr * HZ + jj] = dn;
    }
    asm volatile("bar.sync 1, 256;" ::: "memory");

    ull aa[4];
#pragma unroll
    for (int r = 0; r < 4; ++r) aa[r] = 0;
#pragma unroll 2
    for (int hq = 0; hq < 32; ++hq) {
        ulonglong2 wv = swA[hq * 128 + jj];
        __half2* hw = (__half2*)&wv;
        ull wd01 = h2f2(hw[0]), wd23 = h2f2(hw[1]);
        ull wc01 = h2f2(hw[2]), wc23 = h2f2(hw[3]);
#pragma unroll
        for (int r = 0; r < 4; ++r) {
            int blr = base + q + 2 * r;
            float4 dd = *(const float4*)&sdN[blr * HZ + 4 * hq];
            float4 cc = *(const float4*)&sc[blr * HZ + 4 * hq];
            ffma2(aa[r], pack2(dd.x, dd.y), wd01);
            ffma2(aa[r], pack2(dd.z, dd.w), wd23);
            ffma2(aa[r], pack2(cc.x, cc.y), wc01);
            ffma2(aa[r], pack2(cc.z, cc.w), wc23);
        }
    }
#pragma unroll
    for (int r = 0; r < 4; ++r)
        sah[(base + q + 2 * r) * HZ + jj] = __float2half(hsum(aa[r]));
}

__global__ void __launch_bounds__(NT, 1)
k_main(const float* __restrict__ Y,
       const float* __restrict__ W2,
       const float* __restrict__ W_ih,
       const float* __restrict__ b_ih,
       const float* __restrict__ b_hh,
       const float* __restrict__ fcW,
       const float* __restrict__ fcb,
       const float* __restrict__ fcfW,
       const float* __restrict__ fcfb,
       float* __restrict__ out) {
    extern __shared__ char smraw[];
    ulonglong2* swGa = (ulonglong2*)smraw;
    ulonglong2* swGb = swGa + 4096;
    ulonglong2* swA  = swGb + 4096;
    __half*  sah   = (__half*)(smraw + SM_SA);
    float*   sd    = (float*)(smraw + SM_SD);
    float*   sc    = (float*)(smraw + SM_SC);
    __half2* shfc2 = (__half2*)(smraw + SM_HFC);
    float*   sw2   = (float*)(smraw + SM_W2);
    float*   sy    = (float*)(smraw + SM_SY);
    float*   sctxd = (float*)(smraw + SM_CTXD);

    int tid = threadIdx.x, w = tid >> 5, lane = tid & 31;
    int b0 = blockIdx.x * NB;
    bool is_attn = (tid < 256);

    for (int i = tid; i < 12288; i += NT)
        ((ulonglong2*)smraw)[i] = g_fW[i];
    for (int i = tid; i < NB * HZ; i += NT) {
        sah[i] = __float2half(0.0f);
        sd[i] = 0.0f; sc[i] = 0.0f;
    }
    for (int i = tid; i < NB * Tz / 2; i += NT)
        shfc2[i] = ((const __half2*)g_hfc)[b0 * 32 + i];
    if (tid < FZ) sw2[tid] = __ldg(&W2[tid]);

    int tid2 = tid & 255;
    int jj = tid2 & 127, q = tid2 >> 7;
    float wih0 = __ldg(&W_ih[jj]),        wih1 = __ldg(&W_ih[jj + 128]);
    float wih2 = __ldg(&W_ih[jj + 256]),  wih3 = __ldg(&W_ih[jj + 384]);
    float bia0 = __ldg(&b_ih[jj])       + __ldg(&b_hh[jj]);
    float bia1 = __ldg(&b_ih[jj + 128]) + __ldg(&b_hh[jj + 128]);
    float bia2 = __ldg(&b_ih[jj + 256]) + __ldg(&b_hh[jj + 256]);
    float bia3 = __ldg(&b_ih[jj + 384]) + __ldg(&b_hh[jj + 384]);
    float fwy = __ldg(&fcW[HZ]), fb0 = __ldg(&fcb[0]);

    __syncthreads();

    const __half2* sah2 = (const __half2*)sah;
    for (int t = 0; t < Tz; ++t) {
        if (is_attn) {
            attn_row(w, b0 + w, t, lane, t == Tz - 1,
                     sah2, sw2, shfc2, sy, sctxd, Y, fwy, fb0, fcfW);
        } else if (t > 0) {
            gates_group(8, t - 1, jj, q, swGa, swGb, swA, sd, sc, sah, sy,
                        wih0, wih1, wih2, wih3, bia0, bia1, bia2, bia3);
        }
        __syncthreads();
        if (is_attn) {
            attn_row(8 + w, b0 + 8 + w, t, lane, t == Tz - 1,
                     sah2, sw2, shfc2, sy, sctxd, Y, fwy, fb0, fcfW);
        } else {
            gates_group(0, t, jj, q, swGa, swGb, swA, sd, sc, sah, sy,
                        wih0, wih1, wih2, wih3, bia0, bia1, bia2, bia3);
        }
        __syncthreads();
    }
    if (!is_attn) {
        gates_group(8, Tz - 1, jj, q, swGa, swGb, swA, sd, sc, sah, sy,
                    wih0, wih1, wih2, wih3, bia0, bia1, bia2, bia3);
    }
    __syncthreads();

    {
        int row = w;
        float4 fa = *(const float4*)&fcfW[4 * lane];
        float4 dd = *(const float4*)&sd[row * HZ + 4 * lane];
        float s = dd.x * fa.x + dd.y * fa.y + dd.z * fa.z + dd.w * fa.w;
        s = wred(s);
        if (lane == 0) out[b0 + row] = s + sctxd[row] + __ldg(&fcfb[0]);
    }
}

extern "C" void kernel_launch(void* const* d_in, const int* in_sizes, int n_in,
                              void* d_out, int out_size) {
    (void)in_sizes; (void)n_in; (void)out_size;
    const float* H    = (const float*)d_in[0];
    const float* Y    = (const float*)d_in[1];
    const float* W1   = (const float*)d_in[2];
    const float* b1   = (const float*)d_in[3];
    const float* W2   = (const float*)d_in[4];
    // d_in[5] = attn_b2: cancels in softmax.
    const float* W_ih = (const float*)d_in[6];
    const float* Whh  = (const float*)d_in[7];
    const float* b_ih = (const float*)d_in[8];
    const float* b_hh = (const float*)d_in[9];
    const float* fcW  = (const float*)d_in[10];
    const float* fcb  = (const float*)d_in[11];
    const float* fcfW = (const float*)d_in[12];
    const float* fcfb = (const float*)d_in[13];
    float* out = (float*)d_out;

    static int configured = 0;
    if (!configured) {
        cudaFuncSetAttribute(k_init, cudaFuncAttributeMaxDynamicSharedMemorySize, SMEM_INIT);
        cudaFuncSetAttribute(k_main, cudaFuncAttributeMaxDynamicSharedMemorySize, SMEM_MAIN);
        configured = 1;
    }

    k_tr<<<dim3(4, 16), dim3(32, 8)>>>(Whh);
    k_pack<<<48, 256>>>(W1);
    k_init<<<Bz, 256, SMEM_INIT>>>(H, W1, b1, fcW);
    k_main<<<Bz / NB, NT, SMEM_MAIN>>>(Y, W2, W_ih, b_ih, b_hh, fcW, fcb, fcfW, fcfb, out);
}

// round 8
// speedup vs baseline: 2.7188x; 1.5928x over previous
#include <cuda_runtime.h>
#include <cuda_fp16.h>
#include <math.h>

#define Bz   2048
#define Tz   64
#define HZ   128   // HID
#define FZ   128   // FEAT
#define NB   16    // batch rows per persistent CTA
#define NT   512   // threads per CTA

typedef unsigned long long ull;
typedef unsigned uint32;

// ---------------- scratch (static device globals) ----------------
__device__ unsigned   g_sPT[(size_t)Bz * 4096];   // [b][fp*64+ln*2+par] half2(t0,t1) (32 MB)
__device__ ulonglong2 g_HhP[(size_t)Bz * 1024];   // [b][tp*32+lane] fp16 H packed (32 MB)
__device__ float      g_WhT[HZ * 4 * HZ];         // Whh^T [128h][512j]
__device__ ulonglong2 g_fW[12288];                // fp16 ldmatrix-tiled weights (192 KB)
__device__ __half     g_hfc[(size_t)Bz * Tz];     // H[b,t]·fcW  (256 KB)

// ---------------- helpers ----------------
__device__ __forceinline__ float wred(float v) {
#pragma unroll
    for (int o = 16; o > 0; o >>= 1) v += __shfl_xor_sync(0xffffffffu, v, o);
    return v;
}
__device__ __forceinline__ float fast_tanh(float x) {
    float e = __expf(2.0f * x);
    return 1.0f - __fdividef(2.0f, e + 1.0f);
}
__device__ __forceinline__ __half2 htanh2(__half2 x) {
    unsigned xi = *(unsigned*)&x, r;
    asm("tanh.approx.f16x2 %0, %1;" : "=r"(r) : "r"(xi));
    return *(__half2*)&r;
}
__device__ __forceinline__ float sigm(float x) {
    return __fdividef(1.0f, 1.0f + __expf(-x));
}
__device__ __forceinline__ ull pack2(float a, float b) {
    return (ull)__float_as_uint(a) | ((ull)__float_as_uint(b) << 32);
}
__device__ __forceinline__ float lo2(ull v) { return __uint_as_float((unsigned)v); }
__device__ __forceinline__ float hi2(ull v) { return __uint_as_float((unsigned)(v >> 32)); }
__device__ __forceinline__ void ffma2(ull &acc, ull a, ull b) {
    asm("fma.rn.f32x2 %0, %1, %2, %0;" : "+l"(acc) : "l"(a), "l"(b));
}

// ---- tensor-core primitives ----
__device__ __forceinline__ void ldsm4(uint32 &r0, uint32 &r1, uint32 &r2, uint32 &r3, uint32 addr) {
    asm volatile("ldmatrix.sync.aligned.m8n8.x4.shared.b16 {%0,%1,%2,%3}, [%4];"
        : "=r"(r0), "=r"(r1), "=r"(r2), "=r"(r3) : "r"(addr));
}
__device__ __forceinline__ void ldsm4t(uint32 &r0, uint32 &r1, uint32 &r2, uint32 &r3, uint32 addr) {
    asm volatile("ldmatrix.sync.aligned.m8n8.x4.trans.shared.b16 {%0,%1,%2,%3}, [%4];"
        : "=r"(r0), "=r"(r1), "=r"(r2), "=r"(r3) : "r"(addr));
}
__device__ __forceinline__ void mma16816(float4 &d, uint32 a0, uint32 a1, uint32 a2, uint32 a3,
                                         uint32 b0, uint32 b1) {
    asm volatile("mma.sync.aligned.m16n8k16.row.col.f32.f16.f16.f32 "
        "{%0,%1,%2,%3}, {%4,%5,%6,%7}, {%8,%9}, {%0,%1,%2,%3};"
        : "+f"(d.x), "+f"(d.y), "+f"(d.z), "+f"(d.w)
        : "r"(a0), "r"(a1), "r"(a2), "r"(a3), "r"(b0), "r"(b1));
}

// ---------------------------------------------------------------------------
// k_tr: tiled transpose Whh [512,128] -> g_WhT [128,512]
// ---------------------------------------------------------------------------
__global__ void k_tr(const float* __restrict__ Whh) {
    __shared__ float tile[32][33];
    int tx = threadIdx.x, ty = threadIdx.y;
    int x = blockIdx.x * 32 + tx;
    int y = blockIdx.y * 32 + ty;
#pragma unroll
    for (int k = 0; k < 32; k += 8)
        tile[ty + k][tx] = Whh[(y + k) * HZ + x];
    __syncthreads();
    int x2 = blockIdx.y * 32 + tx;
    int y2 = blockIdx.x * 32 + ty;
#pragma unroll
    for (int k = 0; k < 32; k += 8)
        g_WhT[(y2 + k) * 512 + x2] = tile[tx][ty + k];
}

// ---------------------------------------------------------------------------
// k_pack: ldmatrix-tiled fp16 weights. One ulonglong2 = one 16-byte tile row.
// gates region (idx<8192): tile=((wg*8+G*2+half)*16+kt), row kr:
//   val(nc) = WhT[(kt*8+kr)*512 + G*128 + wg*16 + half*8 + nc]
// a_next region: tile=((wg*2+ng)*32+kt), row kr:
//   val(nc) = W1[(kt*8+kr)*128 + wg*16 + ng*8 + nc]
// ---------------------------------------------------------------------------
__global__ void k_pack(const float* __restrict__ W1) {
    int idx = blockIdx.x * 256 + threadIdx.x;   // 0..12287
    union { ulonglong2 v; __half h[8]; } u;
    if (idx < 8192) {
        int kr = idx & 7, tile = idx >> 3;
        int kt = tile & 15, ng8 = (tile >> 4) & 7, wg = tile >> 7;
        int G = ng8 >> 1, half = ng8 & 1;
        int k = kt * 8 + kr;
        int jb = G * 128 + wg * 16 + half * 8;
#pragma unroll
        for (int nc = 0; nc < 8; ++nc)
            u.h[nc] = __float2half(g_WhT[k * 512 + jb + nc]);
    } else {
        int e = idx - 8192;
        int kr = e & 7, tile = e >> 3;
        int kt = tile & 31, ng = (tile >> 5) & 1, wg = tile >> 6;
        int k = kt * 8 + kr;
        int jb = wg * 16 + ng * 8;
#pragma unroll
        for (int nc = 0; nc < 8; ++nc)
            u.h[nc] = __float2half(__ldg(&W1[k * 128 + jb + nc]));
    }
    g_fW[idx] = u.v;
}

// ---------------------------------------------------------------------------
// k_init: sP GEMM -> g_sPT; fp16 H -> g_HhP; hfc = H·fcW -> g_hfc
// ---------------------------------------------------------------------------
#define SMEM_INIT (HZ * 68 * 4 + 32 * 129 * 4)
__global__ void k_init(const float* __restrict__ H,
                       const float* __restrict__ W1,
                       const float* __restrict__ b1,
                       const float* __restrict__ fcW) {
    extern __shared__ char smraw[];
    float*    sHT    = (float*)smraw;                    // [128h][68pad]
    unsigned* sStage = (unsigned*)(smraw + HZ * 68 * 4); // [32tp][129pad]
    int b = blockIdx.x, tid = threadIdx.x;
    const float* Hb = H + (size_t)b * Tz * HZ;
    for (int i = tid; i < Tz * HZ; i += 256) {
        int t = i >> 7, h = i & 127;
        sHT[h * 68 + t] = Hb[i];
    }
    __syncthreads();

    if (tid < Tz) {
        float acc = 0.0f;
#pragma unroll 4
        for (int f = 0; f < HZ; ++f)
            acc += sHT[f * 68 + tid] * __ldg(&fcW[f]);
        g_hfc[(size_t)b * Tz + tid] = __float2half(acc);
    }

    int f = tid & 127, half_id = tid >> 7;
    float bias = __ldg(&b1[f]);
    ull acc[16];
#pragma unroll
    for (int k = 0; k < 16; ++k) acc[k] = pack2(bias, bias);

#pragma unroll 2
    for (int h = 0; h < HZ; ++h) {
        float w = __ldg(&W1[(256 + h) * FZ + f]);
        ull ww = pack2(w, w);
        const ull* row = (const ull*)&sHT[h * 68];
#pragma unroll
        for (int k = 0; k < 16; ++k)
            ffma2(acc[k], row[half_id * 16 + k], ww);
    }
#pragma unroll
    for (int k = 0; k < 16; ++k) {
        int tp = half_id * 16 + k;
        __half2 hv = __floats2half2_rn(lo2(acc[k]), hi2(acc[k]));
        sStage[tp * 129 + f] = *(unsigned*)&hv;
    }
    __syncthreads();

    unsigned* dst = g_sPT + (size_t)b * 4096;
    for (int i = tid; i < 4096; i += 256) {
        int par = i & 1, ln = (i >> 1) & 31, fp = i >> 6;
        dst[i] = sStage[ln * 129 + 2 * fp + par];
    }
    ulonglong2* hdst = g_HhP + (size_t)b * 1024;
    for (int i = tid; i < 1024; i += 256) {
        int tp = i >> 5, lane = i & 31;
        union { ull u; __half h[4]; } ux, uy;
#pragma unroll
        for (int e = 0; e < 4; ++e) {
            int ff = 4 * lane + e;
            ux.h[e] = __float2half(sHT[ff * 68 + 2 * tp]);
            uy.h[e] = __float2half(sHT[ff * 68 + 2 * tp + 1]);
        }
        hdst[i] = make_ulonglong2(ux.u, uy.u);
    }
}

// ---------------------------------------------------------------------------
// k_main: P1 = all 16 warps attention (1 row each);
//         P2 = warps 0-7: HMMA gates (m16n512k128) + pointwise + HMMA a_next.
// ---------------------------------------------------------------------------
// smem byte offsets
#define SM_WGT   0                 // 192 KB tiled weights (gates 128K, a_next at +131072)
#define SM_SAH   196608            // half[16*128] a                      4096
#define SM_SDH0  200704            // half d buf0 [16 rows x 136 stride]  4352
#define SM_SDH1  205056            // half d buf1                         4352
#define SM_SCH   209408            // half c (for a_next A)               4352
#define SM_SCF   213760            // float c-state [16 x 132 stride]     8448
#define SM_HFC   222208            // half[16*64]                         2048
#define SM_W2    224256            // float[128]                           512
#define SM_WIH   224768            // float[512]                          2048
#define SM_BIA   226816            // float[512]                          2048
#define SM_SY    228864            // float[16]
#define SM_CTXD  228928            // float[16]
#define SMEM_MAIN 228992

#define RB_H 136   // half row stride for sdh/sch
#define RB_F 132   // float row stride for scf

__device__ __forceinline__ void attn_row(
    int row, int b, int t, int lane, bool do_ctx,
    const __half2* sah2, const float* sw2, const __half2* shfc2,
    float* sy, float* sctxd,
    const float* __restrict__ Y, float fwy, float fb0,
    const float* __restrict__ fcfW)
{
    const uint2* pT = (const uint2*)(g_sPT + (size_t)b * 4096);
    const __half2* sar = sah2 + row * 64;
    float s0 = 0.0f, s1 = 0.0f;
#pragma unroll 8
    for (int fp = 0; fp < 64; ++fp) {
        uint2 pv = __ldcs(&pT[fp * 32 + lane]);
        __half2 a01 = sar[fp];
        float2 wf = *(const float2*)&sw2[2 * fp];
        __half2 h0 = *(__half2*)&pv.x, h1 = *(__half2*)&pv.y;
        __half2 t0 = htanh2(__hadd2(h0, __half2half2(__low2half(a01))));
        __half2 t1 = htanh2(__hadd2(h1, __half2half2(__high2half(a01))));
        float2 f0 = __half22float2(t0), f1 = __half22float2(t1);
        s0 += f0.x * wf.x + f1.x * wf.y;
        s1 += f0.y * wf.x + f1.y * wf.y;
    }
    float m = fmaxf(s0, s1);
#pragma unroll
    for (int o = 16; o > 0; o >>= 1) m = fmaxf(m, __shfl_xor_sync(0xffffffffu, m, o));
    float e0 = __expf(s0 - m), e1 = __expf(s1 - m);
    float ssum = wred(e0 + e1);
    float inv = __fdividef(1.0f, ssum);
    float beta0 = e0 * inv, beta1 = e1 * inv;

    float2 hc = __half22float2(shfc2[row * 32 + lane]);
    float part = beta0 * hc.x + beta1 * hc.y;
    part = wred(part);
    if (lane == 0)
        sy[row] = part + __ldg(&Y[b * Tz + t]) * fwy + fb0;

    if (do_ctx) {
        const ulonglong2* HbP = g_HhP + (size_t)b * 1024;
        float c0 = 0.f, c1 = 0.f, c2 = 0.f, c3 = 0.f;
#pragma unroll 4
        for (int tp = 0; tp < 32; ++tp) {
            float bbA = __shfl_sync(0xffffffffu, beta0, tp);
            float bbB = __shfl_sync(0xffffffffu, beta1, tp);
            ulonglong2 hv = __ldcs(&HbP[tp * 32 + lane]);
            __half2* hh = (__half2*)&hv;
            float2 a0 = __half22float2(hh[0]), a1 = __half22float2(hh[1]);
            float2 g0 = __half22float2(hh[2]), g1 = __half22float2(hh[3]);
            c0 += bbA * a0.x + bbB * g0.x;
            c1 += bbA * a0.y + bbB * g0.y;
            c2 += bbA * a1.x + bbB * g1.x;
            c3 += bbA * a1.y + bbB * g1.y;
        }
        float4 f2 = *(const float4*)&fcfW[128 + 4 * lane];
        float cd = c0 * f2.x + c1 * f2.y + c2 * f2.z + c3 * f2.w;
        cd = wred(cd);
        if (lane == 0) sctxd[row] = cd;
    }
}

__global__ void __launch_bounds__(NT, 1)
k_main(const float* __restrict__ Y,
       const float* __restrict__ W2,
       const float* __restrict__ W_ih,
       const float* __restrict__ b_ih,
       const float* __restrict__ b_hh,
       const float* __restrict__ fcW,
       const float* __restrict__ fcb,
       const float* __restrict__ fcfW,
       const float* __restrict__ fcfb,
       float* __restrict__ out) {
    extern __shared__ char smraw[];
    uint32 smem0 = (uint32)__cvta_generic_to_shared(smraw);
    __half*  sah   = (__half*)(smraw + SM_SAH);
    __half*  sch   = (__half*)(smraw + SM_SCH);
    float*   scf   = (float*)(smraw + SM_SCF);
    __half2* shfc2 = (__half2*)(smraw + SM_HFC);
    float*   sw2   = (float*)(smraw + SM_W2);
    float*   swih  = (float*)(smraw + SM_WIH);
    float*   sbia  = (float*)(smraw + SM_BIA);
    float*   sy    = (float*)(smraw + SM_SY);
    float*   sctxd = (float*)(smraw + SM_CTXD);

    int tid = threadIdx.x, w = tid >> 5, lane = tid & 31;
    int b0 = blockIdx.x * NB;
    int g = lane >> 2, tig = lane & 3;
    bool is_mma = (w < 8);
    int wg = w;   // mma warp id 0-7

    // one-time loads
    for (int i = tid; i < 12288; i += NT)
        ((ulonglong2*)smraw)[i] = g_fW[i];
    for (int i = tid; i < NB * HZ; i += NT)
        sah[i] = __float2half(0.0f);
    {
        __half z = __float2half(0.0f);
        __half* sdh0 = (__half*)(smraw + SM_SDH0);
        __half* sdh1 = (__half*)(smraw + SM_SDH1);
        for (int i = tid; i < NB * RB_H; i += NT) { sdh0[i] = z; sdh1[i] = z; sch[i] = z; }
        for (int i = tid; i < NB * RB_F; i += NT) scf[i] = 0.0f;
    }
    for (int i = tid; i < NB * Tz / 2; i += NT)
        shfc2[i] = ((const __half2*)g_hfc)[b0 * 32 + i];
    if (tid < FZ) sw2[tid] = __ldg(&W2[tid]);
    for (int i = tid; i < 512; i += NT) {
        swih[i] = __ldg(&W_ih[i]);
        sbia[i] = __ldg(&b_ih[i]) + __ldg(&b_hh[i]);
    }

    float fwy = __ldg(&fcW[HZ]), fb0 = __ldg(&fcb[0]);
    __syncthreads();

    const __half2* sah2 = (const __half2*)sah;
    for (int t = 0; t < Tz; ++t) {
        // ================= P1: attention, all 16 warps, 1 row each =======
        attn_row(w, b0 + w, t, lane, t == Tz - 1,
                 sah2, sw2, shfc2, sy, sctxd, Y, fwy, fb0, fcfW);
        __syncthreads();

        // ================= P2: warps 0-7 MMA =============================
        if (is_mma) {
            uint32 sdhP = smem0 + ((t & 1) ? SM_SDH1 : SM_SDH0);
            uint32 sdhN = smem0 + ((t & 1) ? SM_SDH0 : SM_SDH1);
            __half* sdhNg = (__half*)(smraw + ((t & 1) ? SM_SDH0 : SM_SDH1));

            int arow = (lane & 7) + (lane & 8);              // ldmatrix A row
            int acol = ((lane >> 4) & 1) * 8;                // ldmatrix A col-half
            // ---- A frags (d_{t-1}), 8 k-tiles ----
            uint32 A[8][4];
#pragma unroll
            for (int kt = 0; kt < 8; ++kt)
                ldsm4(A[kt][0], A[kt][1], A[kt][2], A[kt][3],
                      sdhP + arow * (RB_H * 2) + (kt * 16 + acol) * 2);

            float yt0 = sy[g], yt1 = sy[g + 8];
#pragma unroll
            for (int half = 0; half < 2; ++half) {
                float4 D[4];
#pragma unroll
                for (int G = 0; G < 4; ++G) D[G] = make_float4(0.f, 0.f, 0.f, 0.f);
#pragma unroll
                for (int G = 0; G < 4; ++G) {
                    uint32 tb = smem0 + ((wg * 8 + G * 2 + half) * 16) * 128
                              + (lane >> 3) * 128 + (lane & 7) * 16;
#pragma unroll
                    for (int kq = 0; kq < 4; ++kq) {
                        uint32 b0r, b1r, b2r, b3r;
                        ldsm4t(b0r, b1r, b2r, b3r, tb + kq * 512);
                        mma16816(D[G], A[2*kq][0],   A[2*kq][1],   A[2*kq][2],   A[2*kq][3],   b0r, b1r);
                        mma16816(D[G], A[2*kq+1][0], A[2*kq+1][1], A[2*kq+1][2], A[2*kq+1][3], b2r, b3r);
                    }
                }
                // ---- pointwise: 2 rows x 2 jj ----
                int jb = wg * 16 + half * 8 + tig * 2;
#pragma unroll
                for (int e = 0; e < 2; ++e) {
                    int jj = jb + e;
                    float wi0 = swih[jj],      bi0 = sbia[jj];
                    float wi1 = swih[jj+128],  bi1 = sbia[jj+128];
                    float wi2 = swih[jj+256],  bi2 = sbia[jj+256];
                    float wi3 = swih[jj+384],  bi3 = sbia[jj+384];
#pragma unroll
                    for (int rr = 0; rr < 2; ++rr) {
                        int row = g + rr * 8;
                        float yt = rr ? yt1 : yt0;
                        float gi = (e ? (rr ? D[0].w : D[0].y) : (rr ? D[0].z : D[0].x)) + yt * wi0 + bi0;
                        float gf = (e ? (rr ? D[1].w : D[1].y) : (rr ? D[1].z : D[1].x)) + yt * wi1 + bi1;
                        float gg = (e ? (rr ? D[2].w : D[2].y) : (rr ? D[2].z : D[2].x)) + yt * wi2 + bi2;
                        float go = (e ? (rr ? D[3].w : D[3].y) : (rr ? D[3].z : D[3].x)) + yt * wi3 + bi3;
                        float cold = scf[row * RB_F + jj];
                        float cn = sigm(gf) * cold + sigm(gi) * fast_tanh(gg);
                        float dn = sigm(go) * fast_tanh(cn);
                        scf[row * RB_F + jj] = cn;
                        sdhNg[row * RB_H + jj] = __float2half(dn);
                        sch[row * RB_H + jj]   = __float2half(cn);
                    }
                }
            }
            // all 128 jj columns must be in sdhN/sch before a_next A-frags
            asm volatile("bar.sync 1, 256;" ::: "memory");

            // ---- a_next: m16 n128 k256 ([dn | cn]) ----
            uint32 schU = smem0 + SM_SCH;
#pragma unroll
            for (int ng = 0; ng < 2; ++ng) {
                float4 Da = make_float4(0.f, 0.f, 0.f, 0.f);
                uint32 tb = smem0 + 131072 + ((wg * 2 + ng) * 32) * 128
                          + (lane >> 3) * 128 + (lane & 7) * 16;
#pragma unroll
                for (int kq = 0; kq < 8; ++kq) {
                    uint32 b0r, b1r, b2r, b3r;
                    ldsm4t(b0r, b1r, b2r, b3r, tb + kq * 512);
                    int m0 = 2 * kq, m1 = 2 * kq + 1;
                    uint32 a0, a1, a2, a3;
                    {
                        uint32 base = (m0 < 8) ? sdhN : schU;
                        int kc = (m0 < 8) ? m0 * 16 : (m0 - 8) * 16;
                        ldsm4(a0, a1, a2, a3, base + arow * (RB_H * 2) + (kc + acol) * 2);
                        mma16816(Da, a0, a1, a2, a3, b0r, b1r);
                    }
                    {
                        uint32 base = (m1 < 8) ? sdhN : schU;
                        int kc = (m1 < 8) ? m1 * 16 : (m1 - 8) * 16;
                        ldsm4(a0, a1, a2, a3, base + arow * (RB_H * 2) + (kc + acol) * 2);
                        mma16816(Da, a0, a1, a2, a3, b2r, b3r);
                    }
                }
                int jb = wg * 16 + ng * 8 + tig * 2;
                sah[g * HZ + jb]           = __float2half(Da.x);
                sah[g * HZ + jb + 1]       = __float2half(Da.y);
                sah[(g + 8) * HZ + jb]     = __float2half(Da.z);
                sah[(g + 8) * HZ + jb + 1] = __float2half(Da.w);
            }
        }
        __syncthreads();
    }

    // ---- final: out[b] = d·fcf[0:128] + ctxd + fcfb ----
    // d(T-1) lives in buffer ((Tz-1+1)&1) = buf0
    {
        const __half* sdh0 = (const __half*)(smraw + SM_SDH0);
        int row = w;
        float4 fa = *(const float4*)&fcfW[4 * lane];
        ull hv = *(const ull*)&sdh0[row * RB_H + 4 * lane];
        __half2* hh = (__half2*)&hv;
        float2 d01 = __half22float2(hh[0]), d23 = __half22float2(hh[1]);
        float s = d01.x * fa.x + d01.y * fa.y + d23.x * fa.z + d23.y * fa.w;
        s = wred(s);
        if (lane == 0) out[b0 + row] = s + sctxd[row] + __ldg(&fcfb[0]);
    }
}

extern "C" void kernel_launch(void* const* d_in, const int* in_sizes, int n_in,
                              void* d_out, int out_size) {
    (void)in_sizes; (void)n_in; (void)out_size;
    const float* H    = (const float*)d_in[0];
    const float* Y    = (const float*)d_in[1];
    const float* W1   = (const float*)d_in[2];
    const float* b1   = (const float*)d_in[3];
    const float* W2   = (const float*)d_in[4];
    // d_in[5] = attn_b2: cancels in softmax.
    const float* W_ih = (const float*)d_in[6];
    const float* Whh  = (const float*)d_in[7];
    const float* b_ih = (const float*)d_in[8];
    const float* b_hh = (const float*)d_in[9];
    const float* fcW  = (const float*)d_in[10];
    const float* fcb  = (const float*)d_in[11];
    const float* fcfW = (const float*)d_in[12];
    const float* fcfb = (const float*)d_in[13];
    float* out = (float*)d_out;

    static int configured = 0;
    if (!configured) {
        cudaFuncSetAttribute(k_init, cudaFuncAttributeMaxDynamicSharedMemorySize, SMEM_INIT);
        cudaFuncSetAttribute(k_main, cudaFuncAttributeMaxDynamicSharedMemorySize, SMEM_MAIN);
        configured = 1;
    }

    k_tr<<<dim3(4, 16), dim3(32, 8)>>>(Whh);
    k_pack<<<48, 256>>>(W1);
    k_init<<<Bz, 256, SMEM_INIT>>>(H, W1, b1, fcW);
    k_main<<<Bz / NB, NT, SMEM_MAIN>>>(Y, W2, W_ih, b_ih, b_hh, fcW, fcb, fcfW, fcfb, out);
}